// round 14
// baseline (speedup 1.0000x reference)
#include <cuda_runtime.h>
#include <cuda_fp16.h>
#include <math.h>
#include <stdint.h>

// ---------------- problem constants ----------------
#define BB    16
#define TT    256
#define MELN  1024
#define DD    512
#define HH    8
#define DHD   64
#define LLAY  4
#define INTERN 2048
#define OUTC  80

// ---------------- scratch (device globals; no allocation allowed) ----------
__device__ float  g_x   [(size_t)BB*MELN*DD];
__device__ __half g_xh  [(size_t)BB*MELN*DD];
__device__ __half g_qkvh[(size_t)BB*MELN*3*DD];
__device__ float  g_ctx [(size_t)BB*MELN*DD];
__device__ __half g_ctxh[(size_t)BB*MELN*DD];
__device__ float  g_t1  [(size_t)BB*MELN*DD];
__device__ __half g_hh  [(size_t)BB*MELN*INTERN];
__device__ float  g_h2  [(size_t)BB*MELN*DD];
__device__ float  g_enc [(size_t)BB*TT*DD];
__device__ float  g_am  [BB*TT];
__device__ float  g_am2 [BB*MELN];
__device__ int    g_cums[BB*TT];
#define WT_QKV   0
#define WT_WO    786432
#define WT_C1    1048576
#define WT_C2    4194304
#define WT_LAYER 7340032
__device__ __half g_wh   [(size_t)WT_LAYER * 8];
__device__ __half g_whOut[OUTC * DD];

// ---------------- small helpers ----------------
__device__ __forceinline__ uint32_t smem_u32(const void* p) {
    uint32_t a;
    asm("{ .reg .u64 t; cvta.to.shared.u64 t, %1; cvt.u32.u64 %0, t; }" : "=r"(a) : "l"(p));
    return a;
}

#define MMA_F16(acc, a0,a1,a2,a3, b0,b1)                                      \
    asm volatile("mma.sync.aligned.m16n8k16.row.col.f32.f16.f16.f32 "         \
                 "{%0,%1,%2,%3},{%4,%5,%6,%7},{%8,%9},{%0,%1,%2,%3};"         \
                 : "+f"(acc[0]), "+f"(acc[1]), "+f"(acc[2]), "+f"(acc[3])     \
                 : "r"(a0), "r"(a1), "r"(a2), "r"(a3), "r"(b0), "r"(b1))

#define LDM_X4(r0,r1,r2,r3, addr)                                             \
    asm volatile("ldmatrix.sync.aligned.m8n8.x4.shared.b16 {%0,%1,%2,%3}, [%4];" \
                 : "=r"(r0), "=r"(r1), "=r"(r2), "=r"(r3) : "r"(addr))

#define CP16(dst, src, sz)                                                    \
    asm volatile("cp.async.cg.shared.global [%0], [%1], 16, %2;"              \
                 :: "r"(dst), "l"(src), "r"(sz) : "memory")
#define CP_COMMIT()  asm volatile("cp.async.commit_group;" ::: "memory")
#define CP_WAIT2()   asm volatile("cp.async.wait_group 2;" ::: "memory")

// ========= weight transpose + fp16 convert (batched over layers via z) =====
__global__ __launch_bounds__(256) void transpose_wh(const float* __restrict__ W,
                                                    __half* __restrict__ WH,
                                                    int K, int N,
                                                    size_t wStride, size_t whStride)
{
    const float* Wl = W + (size_t)blockIdx.z * wStride;
    __half* WHl = WH + (size_t)blockIdx.z * whStride;
    __shared__ float t[32][33];
    int k0 = blockIdx.x * 32, n0 = blockIdx.y * 32;
    int tx = threadIdx.x & 31, ty = threadIdx.x >> 5;
#pragma unroll
    for (int i = 0; i < 4; i++) {
        int r = ty + i * 8;
        t[r][tx] = (n0 + tx < N) ? Wl[(size_t)(k0 + r) * N + n0 + tx] : 0.f;
    }
    __syncthreads();
#pragma unroll
    for (int i = 0; i < 4; i++) {
        int r = ty + i * 8;
        if (n0 + r < N)
            WHl[(size_t)(n0 + r) * K + k0 + tx] = __float2half_rn(t[tx][r]);
    }
}

// ========== cp.async pipelined fp16 GEMM (planar smem, 4-stage) ============
// Planar layout per stage: 4 planes of 16B chunks; addr(c,row)=(c*PS+row)*16B,
// PS = rows+2 -> cp.async stores AND ldmatrix reads both bank-conflict-free.
// Template MI: warp m-tile = MI*16 rows, CTA tile = (MI*32) x 128.
// 256 thr = 8 warps (2m x 4n), 4-stage cp.async (wait_group 2), 2 CTAs/SM.
#define BPS 130
#define B_BYTES (4*BPS*16)               // 8320

template<int MI>
__global__ __launch_bounds__(256, 2) void gemm_h(
    const __half* __restrict__ A, const __half* __restrict__ WT,
    const float* __restrict__ bias, float* __restrict__ C32,
    __half* __restrict__ C16,
    int M, int N, int Ktot, int Kin, int sLog, int conv, int relu,
    int halfOut, int transOut)
{
    constexpr int BM  = MI * 32;
    constexpr int APS = BM + 2;
    constexpr int A_BYTES = 4 * APS * 16;
    constexpr int STAGE_BYTES = A_BYTES + B_BYTES;

    extern __shared__ char sm[];
    const uint32_t sbase = smem_u32(sm);

    const int tid  = threadIdx.x;
    const int warp = tid >> 5, lane = tid & 31;
    const int gid  = lane >> 2, tid4 = lane & 3;
    const int wm   = warp & 1,  wn   = warp >> 1;
    const int bm   = blockIdx.y * BM;
    const int bn   = blockIdx.x * 128;
    const int S    = 1 << sLog;
    const int nst  = Ktot / 32;

    const int lrow = lane & 7;
    const int lsel = lane >> 3;
    const int rowOffA = (lsel & 1) * 8;
    const int chkOffA = (lsel >> 1);       // +1 k-chunk for matrices 2,3
    const int rowOffB = (lsel >> 1) * 8;
    const int chkOffB = (lsel & 1);        // +1 k-chunk for matrices 1,3

    float acc[MI][4][4];
#pragma unroll
    for (int i = 0; i < MI; i++)
#pragma unroll
        for (int j = 0; j < 4; j++)
#pragma unroll
            for (int r = 0; r < 4; r++) acc[i][j][r] = 0.f;

    auto issue_stage = [&](int stg) {
        const int k0    = stg * 32;
        const int tap   = conv ? (k0 / Kin) : 0;
        const int kcol  = k0 - tap * Kin;
        const int shift = conv ? (tap - 1) : 0;
        const uint32_t aB = sbase + (stg & 3) * STAGE_BYTES;
        const uint32_t bB = aB + A_BYTES;
        // A: BM rows x 4 chunks (global: 64B contiguous per row, coalesced)
#pragma unroll
        for (int i = 0; i < BM / 64; i++) {
            int flat = tid + i * 256;
            int row = flat >> 2, cq = flat & 3;
            int gm = bm + row;
            int b = gm >> sLog, l = gm & (S - 1);
            int src = l + shift;
            uint32_t sz = (src >= 0 && src < S) ? 16u : 0u;
            int srcc = (src >= 0 && src < S) ? src : 0;
            const __half* gp = A + (size_t)(((size_t)b << sLog) + srcc) * Kin + kcol + cq * 8;
            CP16(aB + (cq * APS + row) * 16, gp, sz);
        }
        // B: 128 rows x 4 chunks
#pragma unroll
        for (int i = 0; i < 2; i++) {
            int flat = tid + i * 256;
            int nr = flat >> 2, cq = flat & 3;
            int gn = bn + nr;
            uint32_t sz = (gn < N) ? 16u : 0u;
            int gnc = (gn < N) ? gn : (N - 1);
            const __half* gp = WT + (size_t)gnc * Ktot + k0 + cq * 8;
            CP16(bB + (cq * BPS + nr) * 16, gp, sz);
        }
    };

    auto compute = [&](int stg) {
        const uint32_t aB = sbase + (stg & 3) * STAGE_BYTES;
        const uint32_t bB = aB + A_BYTES;
#pragma unroll
        for (int c = 0; c < 2; c++) {
            uint32_t af[MI][4];
#pragma unroll
            for (int mi = 0; mi < MI; mi++) {
                int row = wm * (MI * 16) + mi * 16 + lrow + rowOffA;
                int chk = c * 2 + chkOffA;
                LDM_X4(af[mi][0], af[mi][1], af[mi][2], af[mi][3],
                       aB + (chk * APS + row) * 16);
            }
            uint32_t bf[4][2];
#pragma unroll
            for (int njp = 0; njp < 2; njp++) {
                int row = wn * 32 + njp * 16 + lrow + rowOffB;
                int chk = c * 2 + chkOffB;
                uint32_t r0, r1, r2, r3;
                LDM_X4(r0, r1, r2, r3, bB + (chk * BPS + row) * 16);
                bf[njp * 2][0]     = r0;
                bf[njp * 2][1]     = r1;
                bf[njp * 2 + 1][0] = r2;
                bf[njp * 2 + 1][1] = r3;
            }
#pragma unroll
            for (int mi = 0; mi < MI; mi++)
#pragma unroll
                for (int nj = 0; nj < 4; nj++)
                    MMA_F16(acc[mi][nj], af[mi][0], af[mi][1], af[mi][2], af[mi][3],
                            bf[nj][0], bf[nj][1]);
        }
    };

    issue_stage(0); CP_COMMIT();
    issue_stage(1); CP_COMMIT();
    issue_stage(2); CP_COMMIT();
    for (int s = 0; s < nst; s++) {
        CP_WAIT2();
        __syncthreads();
        if (s + 3 < nst) issue_stage(s + 3);
        CP_COMMIT();
        compute(s);
    }

#pragma unroll
    for (int mi = 0; mi < MI; mi++) {
        int gm0 = bm + wm * (MI*16) + mi * 16 + gid;
#pragma unroll
        for (int nj = 0; nj < 4; nj++) {
            int gn = bn + wn * 32 + nj * 8 + tid4 * 2;
            float b0 = (gn < N) ? bias[gn] : 0.f;
            float b1 = (gn + 1 < N) ? bias[gn + 1] : 0.f;
            float v00 = acc[mi][nj][0] + b0;
            float v01 = acc[mi][nj][1] + b1;
            float v10 = acc[mi][nj][2] + b0;
            float v11 = acc[mi][nj][3] + b1;
            if (relu) {
                v00 = fmaxf(v00, 0.f); v01 = fmaxf(v01, 0.f);
                v10 = fmaxf(v10, 0.f); v11 = fmaxf(v11, 0.f);
            }
            if (transOut) {
                int b0i = gm0 >> sLog, f0 = gm0 & (S - 1);
                int b1i = (gm0 + 8) >> sLog, f1 = (gm0 + 8) & (S - 1);
                if (gn < N) {
                    C32[((size_t)b0i * N + gn) * S + f0] = v00;
                    C32[((size_t)b1i * N + gn) * S + f1] = v10;
                }
                if (gn + 1 < N) {
                    C32[((size_t)b0i * N + gn + 1) * S + f0] = v01;
                    C32[((size_t)b1i * N + gn + 1) * S + f1] = v11;
                }
            } else if (halfOut) {
                *(__half2*)&C16[(size_t)gm0 * N + gn]       = __floats2half2_rn(v00, v01);
                *(__half2*)&C16[(size_t)(gm0 + 8) * N + gn] = __floats2half2_rn(v10, v11);
            } else {
                C32[(size_t)gm0 * N + gn]           = v00;
                C32[(size_t)gm0 * N + gn + 1]       = v01;
                C32[(size_t)(gm0 + 8) * N + gn]     = v10;
                C32[(size_t)(gm0 + 8) * N + gn + 1] = v11;
            }
        }
    }
}

#define H_SMEM_128 (4 * ((4*130*16) + B_BYTES))   // 66560
#define H_SMEM_64  (4 * ((4*66*16)  + B_BYTES))   // 50176

// ============== fused flash attention (full fp16 mma path) ==============
#define FA_SPAD 68
#define FA_HPAD 72
#define FA_F32_FLOATS (128*FA_SPAD + 3*128)
#define FA_SMEM_BYTES (FA_F32_FLOATS*4 + (128+64+64+128)*FA_HPAD*2)

__global__ __launch_bounds__(256) void flash_attn(const __half* __restrict__ qkv,
                                                  const float* __restrict__ am,
                                                  __half* __restrict__ ctx, int S)
{
    extern __shared__ float smf[];
    float* Ss   = smf;
    float* mrow = Ss + 128*FA_SPAD;
    float* lrow = mrow + 128;
    float* arow = lrow + 128;
    __half* Qh = (__half*)(arow + 128);
    __half* Kh = Qh + 128*FA_HPAD;
    __half* Vt = Kh + 64*FA_HPAD;
    __half* Ph = Vt + 64*FA_HPAD;

    const uint32_t qhA = smem_u32(Qh);
    const uint32_t khA = smem_u32(Kh);
    const uint32_t vtA = smem_u32(Vt);
    const uint32_t phA = smem_u32(Ph);

    const int tid  = threadIdx.x;
    const int warp = tid >> 5, lane = tid & 31;
    const int gid  = lane >> 2, tid4 = lane & 3;
    const int wm   = warp & 3, wn = warp >> 2;
    const int bh   = blockIdx.y;
    const int b    = bh >> 3, h = bh & 7;
    const int q0   = blockIdx.x * 128;
    const float* amb = am + b * S;
    const __half* qb = qkv + (size_t)(b * S) * 1536 + h * 64;

    const int lrw  = lane & 7;
    const int lsel = lane >> 3;
    const int rowOffA = (lsel & 1) * 8;
    const int colOffA = (lsel >> 1) * 8;
    const int rowOffB = (lsel >> 1) * 8;
    const int colOffB = (lsel & 1) * 8;

#pragma unroll
    for (int i = 0; i < 4; i++) {
        int idx = tid + i * 256;
        int r = idx >> 3, c8 = idx & 7;
        *(uint4*)&Qh[r * FA_HPAD + c8 * 8] =
            *(const uint4*)&qb[(size_t)(q0 + r) * 1536 + c8 * 8];
    }
    if (tid < 128) { mrow[tid] = -INFINITY; lrow[tid] = 0.f; }

    float oacc[2][4][4];
#pragma unroll
    for (int mi = 0; mi < 2; mi++)
#pragma unroll
        for (int nj = 0; nj < 4; nj++)
#pragma unroll
            for (int r = 0; r < 4; r++) oacc[mi][nj][r] = 0.f;

    const int nkt = S >> 6;
    for (int kt = 0; kt < nkt; kt++) {
        const int k0 = kt * 64;
        __syncthreads();
#pragma unroll
        for (int i = 0; i < 2; i++) {
            int idx = tid + i * 256;
            int r = idx >> 3, c8 = idx & 7;
            const __half* src = &qb[(size_t)(k0 + r) * 1536];
            *(uint4*)&Kh[r * FA_HPAD + c8 * 8] = *(const uint4*)&src[512 + c8 * 8];
            uint4 v = *(const uint4*)&src[1024 + c8 * 8];
            const __half* vh = (const __half*)&v;
#pragma unroll
            for (int j = 0; j < 8; j++)
                Vt[(c8 * 8 + j) * FA_HPAD + r] = vh[j];
        }
        __syncthreads();

        float sacc[2][4][4];
#pragma unroll
        for (int mi = 0; mi < 2; mi++)
#pragma unroll
            for (int nj = 0; nj < 4; nj++)
#pragma unroll
                for (int r = 0; r < 4; r++) sacc[mi][nj][r] = 0.f;
#pragma unroll
        for (int kc = 0; kc < 4; kc++) {
            uint32_t af[2][4];
#pragma unroll
            for (int mi = 0; mi < 2; mi++) {
                uint32_t ap = qhA + ((wm * 32 + mi * 16 + lrw + rowOffA) * FA_HPAD
                                     + kc * 16 + colOffA) * 2;
                LDM_X4(af[mi][0], af[mi][1], af[mi][2], af[mi][3], ap);
            }
            uint32_t bf[4][2];
#pragma unroll
            for (int njp = 0; njp < 2; njp++) {
                uint32_t bp = khA + ((wn * 32 + njp * 16 + lrw + rowOffB) * FA_HPAD
                                     + kc * 16 + colOffB) * 2;
                uint32_t r0, r1, r2, r3;
                LDM_X4(r0, r1, r2, r3, bp);
                bf[njp * 2][0]     = r0;
                bf[njp * 2][1]     = r1;
                bf[njp * 2 + 1][0] = r2;
                bf[njp * 2 + 1][1] = r3;
            }
#pragma unroll
            for (int mi = 0; mi < 2; mi++)
#pragma unroll
                for (int nj = 0; nj < 4; nj++)
                    MMA_F16(sacc[mi][nj], af[mi][0], af[mi][1], af[mi][2], af[mi][3],
                            bf[nj][0], bf[nj][1]);
        }
#pragma unroll
        for (int mi = 0; mi < 2; mi++) {
            int r = wm * 32 + mi * 16 + gid;
#pragma unroll
            for (int nj = 0; nj < 4; nj++) {
                int c = wn * 32 + nj * 8 + tid4 * 2;
                float am0 = amb[k0 + c], am1 = amb[k0 + c + 1];
                Ss[r * FA_SPAD + c]           = sacc[mi][nj][0] * 0.125f + am0;
                Ss[r * FA_SPAD + c + 1]       = sacc[mi][nj][1] * 0.125f + am1;
                Ss[(r + 8) * FA_SPAD + c]     = sacc[mi][nj][2] * 0.125f + am0;
                Ss[(r + 8) * FA_SPAD + c + 1] = sacc[mi][nj][3] * 0.125f + am1;
            }
        }
        __syncthreads();
        {
            int r = tid >> 1, hf = tid & 1;
            float* srow = Ss + r * FA_SPAD + hf * 32;
            __half* prow = Ph + r * FA_HPAD + hf * 32;
            float mx = -INFINITY;
#pragma unroll 8
            for (int j = 0; j < 32; j++) mx = fmaxf(mx, srow[j]);
            mx = fmaxf(mx, __shfl_xor_sync(0xffffffffu, mx, 1));
            float mold = mrow[r];
            float mnew = fmaxf(mold, mx);
            float sum = 0.f;
#pragma unroll 8
            for (int j = 0; j < 32; j++) {
                float pv = __expf(srow[j] - mnew);
                prow[j] = __float2half_rn(pv);
                sum += pv;
            }
            sum += __shfl_xor_sync(0xffffffffu, sum, 1);
            if (hf == 0) {
                float alpha = __expf(mold - mnew);
                lrow[r] = lrow[r] * alpha + sum;
                mrow[r] = mnew;
                arow[r] = alpha;
            }
        }
        __syncthreads();

        float al[2][2];
#pragma unroll
        for (int mi = 0; mi < 2; mi++) {
            int r = wm * 32 + mi * 16 + gid;
            al[mi][0] = arow[r];
            al[mi][1] = arow[r + 8];
        }
#pragma unroll
        for (int mi = 0; mi < 2; mi++)
#pragma unroll
            for (int nj = 0; nj < 4; nj++) {
                oacc[mi][nj][0] *= al[mi][0];
                oacc[mi][nj][1] *= al[mi][0];
                oacc[mi][nj][2] *= al[mi][1];
                oacc[mi][nj][3] *= al[mi][1];
            }
#pragma unroll
        for (int kc = 0; kc < 4; kc++) {
            uint32_t af[2][4];
#pragma unroll
            for (int mi = 0; mi < 2; mi++) {
                uint32_t ap = phA + ((wm * 32 + mi * 16 + lrw + rowOffA) * FA_HPAD
                                     + kc * 16 + colOffA) * 2;
                LDM_X4(af[mi][0], af[mi][1], af[mi][2], af[mi][3], ap);
            }
            uint32_t bf[4][2];
#pragma unroll
            for (int njp = 0; njp < 2; njp++) {
                uint32_t bp = vtA + ((wn * 32 + njp * 16 + lrw + rowOffB) * FA_HPAD
                                     + kc * 16 + colOffB) * 2;
                uint32_t r0, r1, r2, r3;
                LDM_X4(r0, r1, r2, r3, bp);
                bf[njp * 2][0]     = r0;
                bf[njp * 2][1]     = r1;
                bf[njp * 2 + 1][0] = r2;
                bf[njp * 2 + 1][1] = r3;
            }
#pragma unroll
            for (int mi = 0; mi < 2; mi++)
#pragma unroll
                for (int nj = 0; nj < 4; nj++)
                    MMA_F16(oacc[mi][nj], af[mi][0], af[mi][1], af[mi][2], af[mi][3],
                            bf[nj][0], bf[nj][1]);
        }
    }
#pragma unroll
    for (int mi = 0; mi < 2; mi++) {
        int r = wm * 32 + mi * 16 + gid;
        float inv0 = 1.f / lrow[r];
        float inv1 = 1.f / lrow[r + 8];
#pragma unroll
        for (int nj = 0; nj < 4; nj++) {
            int c = wn * 32 + nj * 8 + tid4 * 2;
            __half2* o0 = (__half2*)&ctx[(size_t)(b * S + q0 + r) * DD + h * 64 + c];
            __half2* o1 = (__half2*)&ctx[(size_t)(b * S + q0 + r + 8) * DD + h * 64 + c];
            *o0 = __floats2half2_rn(oacc[mi][nj][0] * inv0, oacc[mi][nj][1] * inv0);
            *o1 = __floats2half2_rn(oacc[mi][nj][2] * inv1, oacc[mi][nj][3] * inv1);
        }
    }
}

// ---------------- embed + positional (reference adds pos[b], not pos[t]) ----
__global__ __launch_bounds__(256) void embed_kernel(const int* __restrict__ tokens,
                                                    const float* __restrict__ emb,
                                                    float* __restrict__ x,
                                                    __half* __restrict__ xh)
{
    int i = blockIdx.x * 256 + threadIdx.x;
    if (i >= BB*TT*DD) return;
    int d  = i & (DD-1);
    int bt = i / DD;
    int b  = bt / TT;
    int tok = tokens[bt];
    int half = d >> 1;
    float den = __expf(-(float)(2*half) * (logf(10000.f) / (float)DD));
    float ang = (float)b * den;
    float posv = (d & 1) ? cosf(ang) : sinf(ang);
    float v = 2.f * emb[(size_t)tok*DD + d] + posv;
    x[i] = v;
    xh[i] = __float2half_rn(v);
}

__global__ __launch_bounds__(256) void mask_kernel(const int* __restrict__ lens,
                                                   float* __restrict__ am, int S)
{
    int i = blockIdx.x*256 + threadIdx.x;
    if (i >= BB*S) return;
    int b = i / S, t = i % S;
    am[i] = (t > lens[b]) ? -INFINITY : 0.f;
}

__global__ __launch_bounds__(256) void add_ln_kernel(const float* __restrict__ resid,
                                                     const float* __restrict__ delta,
                                                     const float* __restrict__ g,
                                                     const float* __restrict__ bb,
                                                     float* __restrict__ out,
                                                     __half* __restrict__ outh)
{
    size_t row = blockIdx.x;
    int t = threadIdx.x;
    __shared__ float red[256];
    float v0 = resid[row*DD + t]       + delta[row*DD + t];
    float v1 = resid[row*DD + t + 256] + delta[row*DD + t + 256];
    red[t] = v0 + v1; __syncthreads();
    for (int s = 128; s > 0; s >>= 1) { if (t < s) red[t] += red[t+s]; __syncthreads(); }
    float mean = red[0] * (1.f/DD);
    __syncthreads();
    float d0 = v0 - mean, d1 = v1 - mean;
    red[t] = d0*d0 + d1*d1; __syncthreads();
    for (int s = 128; s > 0; s >>= 1) { if (t < s) red[t] += red[t+s]; __syncthreads(); }
    float var = red[0] * (1.f/DD);
    float sc = rsqrtf(var + 1e-5f);
    float o0 = d0*sc*g[t]     + bb[t];
    float o1 = d1*sc*g[t+256] + bb[t+256];
    out[row*DD + t]        = o0;
    out[row*DD + t + 256]  = o1;
    outh[row*DD + t]       = __float2half_rn(o0);
    outh[row*DD + t + 256] = __float2half_rn(o1);
}

__global__ void cumsum_kernel(const int* __restrict__ dur, int* __restrict__ cums)
{
    int b = blockIdx.x;
    if (threadIdx.x == 0) {
        int s = 0;
        for (int t = 0; t < TT; t++) { s += dur[b*TT + t]; cums[b*TT + t] = s; }
    }
}

__global__ __launch_bounds__(256) void regulate_kernel(const float* __restrict__ enc,
                                                       const int* __restrict__ cums,
                                                       const int* __restrict__ mellen,
                                                       float* __restrict__ dec_in,
                                                       __half* __restrict__ dec_inh)
{
    int bf = blockIdx.x;
    int b = bf / MELN, f = bf % MELN;
    const int* c = cums + b*TT;
    int lo = 0, hi = TT;
    while (lo < hi) { int mid = (lo + hi) >> 1; if (c[mid] <= f) lo = mid + 1; else hi = mid; }
    int idx = lo; if (idx > TT-1) idx = TT-1;
    float keep = (f <= mellen[b]) ? 1.f : 0.f;
    for (int d = threadIdx.x; d < DD; d += 256) {
        float v = enc[(size_t)(b*TT + idx)*DD + d] * keep;
        dec_in[(size_t)bf*DD + d]  = v;
        dec_inh[(size_t)bf*DD + d] = __float2half_rn(v);
    }
}

// =============================== host side ===============================
struct Ptrs {
    float *x, *ctx, *t1, *h2, *enc, *am, *am2;
    __half *xh, *qkvh, *ctxh, *hh, *wh, *whOut;
    int *cums;
};

static void get_ptrs(Ptrs& p)
{
    cudaGetSymbolAddress((void**)&p.x,     g_x);
    cudaGetSymbolAddress((void**)&p.xh,    g_xh);
    cudaGetSymbolAddress((void**)&p.qkvh,  g_qkvh);
    cudaGetSymbolAddress((void**)&p.ctx,   g_ctx);
    cudaGetSymbolAddress((void**)&p.ctxh,  g_ctxh);
    cudaGetSymbolAddress((void**)&p.t1,    g_t1);
    cudaGetSymbolAddress((void**)&p.hh,    g_hh);
    cudaGetSymbolAddress((void**)&p.h2,    g_h2);
    cudaGetSymbolAddress((void**)&p.enc,   g_enc);
    cudaGetSymbolAddress((void**)&p.am,    g_am);
    cudaGetSymbolAddress((void**)&p.am2,   g_am2);
    cudaGetSymbolAddress((void**)&p.wh,    g_wh);
    cudaGetSymbolAddress((void**)&p.whOut, g_whOut);
    cudaGetSymbolAddress((void**)&p.cums,  g_cums);
}

static void run_layer(Ptrs& p, int S, int sLog, const float* am, const __half* whl,
                      const float* bqkv, const float* bo,
                      const float* ln1g, const float* ln1b,
                      const float* c1b,  const float* c2b,
                      const float* ln2g, const float* ln2b)
{
    const int M = BB * S;
    const bool small = (S == TT);

    if (small)
        gemm_h<2><<<dim3(12, M/64), 256, H_SMEM_64>>>(p.xh, whl + WT_QKV, bqkv,
                                                      nullptr, p.qkvh,
                                                      M, 3*DD, DD, DD, sLog, 0, 0, 1, 0);
    else
        gemm_h<4><<<dim3(12, M/128), 256, H_SMEM_128>>>(p.xh, whl + WT_QKV, bqkv,
                                                        nullptr, p.qkvh,
                                                        M, 3*DD, DD, DD, sLog, 0, 0, 1, 0);

    flash_attn<<<dim3(S/128, BB*HH), 256, FA_SMEM_BYTES>>>(p.qkvh, am, p.ctxh, S);

    if (small)
        gemm_h<2><<<dim3(4, M/64), 256, H_SMEM_64>>>(p.ctxh, whl + WT_WO, bo,
                                                     p.t1, nullptr,
                                                     M, DD, DD, DD, sLog, 0, 0, 0, 0);
    else
        gemm_h<4><<<dim3(4, M/128), 256, H_SMEM_128>>>(p.ctxh, whl + WT_WO, bo,
                                                       p.t1, nullptr,
                                                       M, DD, DD, DD, sLog, 0, 0, 0, 0);

    add_ln_kernel<<<M, 256>>>(p.x, p.t1, ln1g, ln1b, p.ctx, p.xh);

    gemm_h<4><<<dim3(16, M/128), 256, H_SMEM_128>>>(p.xh, whl + WT_C1, c1b,
                                                    nullptr, p.hh,
                                                    M, INTERN, 3*DD, DD, sLog, 1, 1, 1, 0);
    if (small)
        gemm_h<2><<<dim3(4, M/64), 256, H_SMEM_64>>>(p.hh, whl + WT_C2, c2b,
                                                     p.h2, nullptr,
                                                     M, DD, 3*INTERN, INTERN, sLog, 1, 0, 0, 0);
    else
        gemm_h<4><<<dim3(4, M/128), 256, H_SMEM_128>>>(p.hh, whl + WT_C2, c2b,
                                                       p.h2, nullptr,
                                                       M, DD, 3*INTERN, INTERN, sLog, 1, 0, 0, 0);

    add_ln_kernel<<<M, 256>>>(p.ctx, p.h2, ln2g, ln2b, p.x, p.xh);
}

extern "C" void kernel_launch(void* const* d_in, const int* in_sizes, int n_in,
                              void* d_out, int out_size)
{
    const int*   tokens        = (const int*)  d_in[0];
    const int*   token_lengths = (const int*)  d_in[1];
    const int*   melspec_len   = (const int*)  d_in[2];
    const int*   durations     = (const int*)  d_in[3];
    const float* emb           = (const float*)d_in[5];
    const float* ew[12]; for (int i = 0; i < 12; i++) ew[i] = (const float*)d_in[6 + i];
    const float* dw[12]; for (int i = 0; i < 12; i++) dw[i] = (const float*)d_in[18 + i];
    const float* out_w         = (const float*)d_in[30];
    const float* out_b         = (const float*)d_in[31];

    cudaFuncSetAttribute(flash_attn, cudaFuncAttributeMaxDynamicSharedMemorySize,
                         FA_SMEM_BYTES);
    cudaFuncSetAttribute(gemm_h<4>, cudaFuncAttributeMaxDynamicSharedMemorySize,
                         H_SMEM_128);
    cudaFuncSetAttribute(gemm_h<2>, cudaFuncAttributeMaxDynamicSharedMemorySize,
                         H_SMEM_64);

    Ptrs p; get_ptrs(p);

    // ---- weight transpose + fp16 convert (batched: blockIdx.z = layer) ----
    for (int half = 0; half < 2; half++) {
        const float* const* w = (half == 0) ? ew : dw;
        __half* whb = p.wh + (size_t)half * LLAY * WT_LAYER;
        transpose_wh<<<dim3(16, 48, LLAY), 256>>>(w[0], whb + WT_QKV, DD, 3*DD,
                                                  (size_t)DD*3*DD, WT_LAYER);
        transpose_wh<<<dim3(16, 16, LLAY), 256>>>(w[2], whb + WT_WO, DD, DD,
                                                  (size_t)DD*DD, WT_LAYER);
        transpose_wh<<<dim3(48, 64, LLAY), 256>>>(w[6], whb + WT_C1, 3*DD, INTERN,
                                                  (size_t)3*DD*INTERN, WT_LAYER);
        transpose_wh<<<dim3(192, 16, LLAY), 256>>>(w[8], whb + WT_C2, 3*INTERN, DD,
                                                   (size_t)3*INTERN*DD, WT_LAYER);
    }
    transpose_wh<<<dim3(16, 3, 1), 256>>>(out_w, p.whOut, DD, OUTC, 0, 0);

    // ---- embed + positional + encoder mask ----
    embed_kernel<<<(BB*TT*DD + 255)/256, 256>>>(tokens, emb, p.x, p.xh);
    mask_kernel<<<(BB*TT + 255)/256, 256>>>(token_lengths, p.am, TT);

    // ---- encoder stack (S = TT) ----
    for (int l = 0; l < LLAY; l++) {
        run_layer(p, TT, 8, p.am, p.wh + (size_t)l * WT_LAYER,
                  ew[1] + (size_t)l*3*DD,  ew[3] + (size_t)l*DD,
                  ew[4] + (size_t)l*DD,    ew[5] + (size_t)l*DD,
                  ew[7] + (size_t)l*INTERN, ew[9] + (size_t)l*DD,
                  ew[10] + (size_t)l*DD,   ew[11] + (size_t)l*DD);
    }

    // ---- length regulator ----
    cudaMemcpyAsync(p.enc, p.x, (size_t)BB*TT*DD*sizeof(float), cudaMemcpyDeviceToDevice);
    cumsum_kernel<<<BB, 32>>>(durations, p.cums);
    regulate_kernel<<<BB*MELN, 256>>>(p.enc, p.cums, melspec_len, p.x, p.xh);
    mask_kernel<<<(BB*MELN + 255)/256, 256>>>(melspec_len, p.am2, MELN);

    // ---- decoder stack (S = MELN) ----
    for (int l = 0; l < LLAY; l++) {
        run_layer(p, MELN, 10, p.am2, p.wh + (size_t)(LLAY + l) * WT_LAYER,
                  dw[1] + (size_t)l*3*DD,  dw[3] + (size_t)l*DD,
                  dw[4] + (size_t)l*DD,    dw[5] + (size_t)l*DD,
                  dw[7] + (size_t)l*INTERN, dw[9] + (size_t)l*DD,
                  dw[10] + (size_t)l*DD,   dw[11] + (size_t)l*DD);
    }

    // ---- output projection fused with transpose: writes (b, o, f) ----
    gemm_h<2><<<dim3(1, BB*MELN/64), 256, H_SMEM_64>>>(p.xh, p.whOut, out_b,
                                                       (float*)d_out, nullptr,
                                                       BB*MELN, OUTC, DD, DD, 10,
                                                       0, 0, 0, 1);
}

// round 15
// speedup vs baseline: 1.4652x; 1.4652x over previous
#include <cuda_runtime.h>
#include <cuda_fp16.h>
#include <math.h>
#include <stdint.h>

// ---------------- problem constants ----------------
#define BB    16
#define TT    256
#define MELN  1024
#define DD    512
#define HH    8
#define DHD   64
#define LLAY  4
#define INTERN 2048
#define OUTC  80

// ---------------- scratch (device globals; no allocation allowed) ----------
__device__ float  g_x   [(size_t)BB*MELN*DD];
__device__ __half g_xh  [(size_t)BB*MELN*DD];
__device__ __half g_qkvh[(size_t)BB*MELN*3*DD];
__device__ float  g_ctx [(size_t)BB*MELN*DD];
__device__ __half g_ctxh[(size_t)BB*MELN*DD];
__device__ float  g_t1  [(size_t)BB*MELN*DD];
__device__ __half g_hh  [(size_t)BB*MELN*INTERN];
__device__ float  g_h2  [(size_t)BB*MELN*DD];
__device__ float  g_enc [(size_t)BB*TT*DD];
__device__ float  g_am  [BB*TT];
__device__ float  g_am2 [BB*MELN];
__device__ int    g_cums[BB*TT];
#define WT_QKV   0
#define WT_WO    786432
#define WT_C1    1048576
#define WT_C2    4194304
#define WT_LAYER 7340032
__device__ __half g_wh   [(size_t)WT_LAYER * 8];
__device__ __half g_whOut[OUTC * DD];

// ---------------- small helpers ----------------
__device__ __forceinline__ uint32_t smem_u32(const void* p) {
    uint32_t a;
    asm("{ .reg .u64 t; cvta.to.shared.u64 t, %1; cvt.u32.u64 %0, t; }" : "=r"(a) : "l"(p));
    return a;
}

#define MMA_F16(acc, a0,a1,a2,a3, b0,b1)                                      \
    asm volatile("mma.sync.aligned.m16n8k16.row.col.f32.f16.f16.f32 "         \
                 "{%0,%1,%2,%3},{%4,%5,%6,%7},{%8,%9},{%0,%1,%2,%3};"         \
                 : "+f"(acc[0]), "+f"(acc[1]), "+f"(acc[2]), "+f"(acc[3])     \
                 : "r"(a0), "r"(a1), "r"(a2), "r"(a3), "r"(b0), "r"(b1))

#define LDM_X4(r0,r1,r2,r3, addr)                                             \
    asm volatile("ldmatrix.sync.aligned.m8n8.x4.shared.b16 {%0,%1,%2,%3}, [%4];" \
                 : "=r"(r0), "=r"(r1), "=r"(r2), "=r"(r3) : "r"(addr))

#define CP16(dst, src, sz)                                                    \
    asm volatile("cp.async.cg.shared.global [%0], [%1], 16, %2;"              \
                 :: "r"(dst), "l"(src), "r"(sz) : "memory")
#define CP_COMMIT()  asm volatile("cp.async.commit_group;" ::: "memory")
#define CP_WAIT2()   asm volatile("cp.async.wait_group 2;" ::: "memory")

// ========= weight transpose + fp16 convert (batched over layers via z) =====
__global__ __launch_bounds__(256) void transpose_wh(const float* __restrict__ W,
                                                    __half* __restrict__ WH,
                                                    int K, int N,
                                                    size_t wStride, size_t whStride)
{
    const float* Wl = W + (size_t)blockIdx.z * wStride;
    __half* WHl = WH + (size_t)blockIdx.z * whStride;
    __shared__ float t[32][33];
    int k0 = blockIdx.x * 32, n0 = blockIdx.y * 32;
    int tx = threadIdx.x & 31, ty = threadIdx.x >> 5;
#pragma unroll
    for (int i = 0; i < 4; i++) {
        int r = ty + i * 8;
        t[r][tx] = (n0 + tx < N) ? Wl[(size_t)(k0 + r) * N + n0 + tx] : 0.f;
    }
    __syncthreads();
#pragma unroll
    for (int i = 0; i < 4; i++) {
        int r = ty + i * 8;
        if (n0 + r < N)
            WHl[(size_t)(n0 + r) * K + k0 + tx] = __float2half_rn(t[tx][r]);
    }
}

// ========== cp.async pipelined fp16 GEMM (R13 layout, 4-stage) =============
// Row layout (validated): smem row = H_STRIDE=40 halves (32 data + 8 pad).
// Template MI: warp m-tile = MI*16 rows, CTA tile = (MI*32) x 128.
// 256 thr = 8 warps (2m x 4n), 4-stage cp.async (wait_group 2), 2 CTAs/SM.
#define H_STRIDE 40
#define HB_HALVES (128*H_STRIDE)

template<int MI>
__global__ __launch_bounds__(256, 2) void gemm_h(
    const __half* __restrict__ A, const __half* __restrict__ WT,
    const float* __restrict__ bias, float* __restrict__ C32,
    __half* __restrict__ C16,
    int M, int N, int Ktot, int Kin, int sLog, int conv, int relu,
    int halfOut, int transOut)
{
    constexpr int BM = MI * 32;
    constexpr int HA_HALVES = BM * H_STRIDE;
    constexpr int STAGE_BYTES = (HA_HALVES + HB_HALVES) * 2;

    extern __shared__ char sm[];
    const uint32_t sbase = smem_u32(sm);

    const int tid  = threadIdx.x;
    const int warp = tid >> 5, lane = tid & 31;
    const int gid  = lane >> 2, tid4 = lane & 3;
    const int wm   = warp & 1,  wn   = warp >> 1;
    const int bm   = blockIdx.y * BM;
    const int bn   = blockIdx.x * 128;
    const int S    = 1 << sLog;
    const int nst  = Ktot / 32;

    const int lrow = lane & 7;
    const int lsel = lane >> 3;
    const int rowOffA = (lsel & 1) * 8;
    const int colOffA = (lsel >> 1) * 8;
    const int rowOffB = (lsel >> 1) * 8;
    const int colOffB = (lsel & 1) * 8;

    float acc[MI][4][4];
#pragma unroll
    for (int i = 0; i < MI; i++)
#pragma unroll
        for (int j = 0; j < 4; j++)
#pragma unroll
            for (int r = 0; r < 4; r++) acc[i][j][r] = 0.f;

    auto issue_stage = [&](int stg) {
        const int k0    = stg * 32;
        const int tap   = conv ? (k0 / Kin) : 0;
        const int kcol  = k0 - tap * Kin;
        const int shift = conv ? (tap - 1) : 0;
        const uint32_t aB = sbase + (stg & 3) * STAGE_BYTES;
        const uint32_t bB = aB + HA_HALVES * 2;
#pragma unroll
        for (int i = 0; i < BM / 64; i++) {
            int flat = tid + i * 256;
            int row = flat >> 2, cq = flat & 3;
            int gm = bm + row;
            int b = gm >> sLog, l = gm & (S - 1);
            int src = l + shift;
            uint32_t sz = (src >= 0 && src < S) ? 16u : 0u;
            int srcc = (src >= 0 && src < S) ? src : 0;
            const __half* gp = A + (size_t)(((size_t)b << sLog) + srcc) * Kin + kcol + cq * 8;
            CP16(aB + (row * H_STRIDE + cq * 8) * 2, gp, sz);
        }
#pragma unroll
        for (int i = 0; i < 2; i++) {
            int flat = tid + i * 256;
            int nr = flat >> 2, cq = flat & 3;
            int gn = bn + nr;
            uint32_t sz = (gn < N) ? 16u : 0u;
            int gnc = (gn < N) ? gn : (N - 1);
            const __half* gp = WT + (size_t)gnc * Ktot + k0 + cq * 8;
            CP16(bB + (nr * H_STRIDE + cq * 8) * 2, gp, sz);
        }
    };

    auto compute = [&](int stg) {
        const uint32_t aB = sbase + (stg & 3) * STAGE_BYTES;
        const uint32_t bB = aB + HA_HALVES * 2;
#pragma unroll
        for (int c = 0; c < 2; c++) {
            uint32_t af[MI][4];
#pragma unroll
            for (int mi = 0; mi < MI; mi++) {
                uint32_t ap = aB + ((wm * (MI*16) + mi * 16 + lrow + rowOffA) * H_STRIDE
                                    + c * 16 + colOffA) * 2;
                LDM_X4(af[mi][0], af[mi][1], af[mi][2], af[mi][3], ap);
            }
            uint32_t bf[4][2];
#pragma unroll
            for (int njp = 0; njp < 2; njp++) {
                uint32_t bp = bB + ((wn * 32 + njp * 16 + lrow + rowOffB) * H_STRIDE
                                    + c * 16 + colOffB) * 2;
                uint32_t r0, r1, r2, r3;
                LDM_X4(r0, r1, r2, r3, bp);
                bf[njp * 2][0]     = r0;
                bf[njp * 2][1]     = r1;
                bf[njp * 2 + 1][0] = r2;
                bf[njp * 2 + 1][1] = r3;
            }
#pragma unroll
            for (int mi = 0; mi < MI; mi++)
#pragma unroll
                for (int nj = 0; nj < 4; nj++)
                    MMA_F16(acc[mi][nj], af[mi][0], af[mi][1], af[mi][2], af[mi][3],
                            bf[nj][0], bf[nj][1]);
        }
    };

    issue_stage(0); CP_COMMIT();
    issue_stage(1); CP_COMMIT();
    issue_stage(2); CP_COMMIT();
    for (int s = 0; s < nst; s++) {
        CP_WAIT2();
        __syncthreads();
        if (s + 3 < nst) issue_stage(s + 3);
        CP_COMMIT();
        compute(s);
    }

#pragma unroll
    for (int mi = 0; mi < MI; mi++) {
        int gm0 = bm + wm * (MI*16) + mi * 16 + gid;
#pragma unroll
        for (int nj = 0; nj < 4; nj++) {
            int gn = bn + wn * 32 + nj * 8 + tid4 * 2;
            float b0 = (gn < N) ? bias[gn] : 0.f;
            float b1 = (gn + 1 < N) ? bias[gn + 1] : 0.f;
            float v00 = acc[mi][nj][0] + b0;
            float v01 = acc[mi][nj][1] + b1;
            float v10 = acc[mi][nj][2] + b0;
            float v11 = acc[mi][nj][3] + b1;
            if (relu) {
                v00 = fmaxf(v00, 0.f); v01 = fmaxf(v01, 0.f);
                v10 = fmaxf(v10, 0.f); v11 = fmaxf(v11, 0.f);
            }
            if (transOut) {
                int b0i = gm0 >> sLog, f0 = gm0 & (S - 1);
                int b1i = (gm0 + 8) >> sLog, f1 = (gm0 + 8) & (S - 1);
                if (gn < N) {
                    C32[((size_t)b0i * N + gn) * S + f0] = v00;
                    C32[((size_t)b1i * N + gn) * S + f1] = v10;
                }
                if (gn + 1 < N) {
                    C32[((size_t)b0i * N + gn + 1) * S + f0] = v01;
                    C32[((size_t)b1i * N + gn + 1) * S + f1] = v11;
                }
            } else if (halfOut) {
                *(__half2*)&C16[(size_t)gm0 * N + gn]       = __floats2half2_rn(v00, v01);
                *(__half2*)&C16[(size_t)(gm0 + 8) * N + gn] = __floats2half2_rn(v10, v11);
            } else {
                C32[(size_t)gm0 * N + gn]           = v00;
                C32[(size_t)gm0 * N + gn + 1]       = v01;
                C32[(size_t)(gm0 + 8) * N + gn]     = v10;
                C32[(size_t)(gm0 + 8) * N + gn + 1] = v11;
            }
        }
    }
}

#define H_SMEM_128 (4 * ((128*H_STRIDE + HB_HALVES) * 2))   // 81920
#define H_SMEM_64  (4 * (( 64*H_STRIDE + HB_HALVES) * 2))   // 61440

// ============== fused flash attention (full fp16 mma path, R13) ============
#define FA_SPAD 68
#define FA_HPAD 72
#define FA_F32_FLOATS (128*FA_SPAD + 3*128)
#define FA_SMEM_BYTES (FA_F32_FLOATS*4 + (128+64+64+128)*FA_HPAD*2)

__global__ __launch_bounds__(256) void flash_attn(const __half* __restrict__ qkv,
                                                  const float* __restrict__ am,
                                                  __half* __restrict__ ctx, int S)
{
    extern __shared__ float smf[];
    float* Ss   = smf;
    float* mrow = Ss + 128*FA_SPAD;
    float* lrow = mrow + 128;
    float* arow = lrow + 128;
    __half* Qh = (__half*)(arow + 128);
    __half* Kh = Qh + 128*FA_HPAD;
    __half* Vt = Kh + 64*FA_HPAD;
    __half* Ph = Vt + 64*FA_HPAD;

    const uint32_t qhA = smem_u32(Qh);
    const uint32_t khA = smem_u32(Kh);
    const uint32_t vtA = smem_u32(Vt);
    const uint32_t phA = smem_u32(Ph);

    const int tid  = threadIdx.x;
    const int warp = tid >> 5, lane = tid & 31;
    const int gid  = lane >> 2, tid4 = lane & 3;
    const int wm   = warp & 3, wn = warp >> 2;
    const int bh   = blockIdx.y;
    const int b    = bh >> 3, h = bh & 7;
    const int q0   = blockIdx.x * 128;
    const float* amb = am + b * S;
    const __half* qb = qkv + (size_t)(b * S) * 1536 + h * 64;

    const int lrw  = lane & 7;
    const int lsel = lane >> 3;
    const int rowOffA = (lsel & 1) * 8;
    const int colOffA = (lsel >> 1) * 8;
    const int rowOffB = (lsel >> 1) * 8;
    const int colOffB = (lsel & 1) * 8;

#pragma unroll
    for (int i = 0; i < 4; i++) {
        int idx = tid + i * 256;
        int r = idx >> 3, c8 = idx & 7;
        *(uint4*)&Qh[r * FA_HPAD + c8 * 8] =
            *(const uint4*)&qb[(size_t)(q0 + r) * 1536 + c8 * 8];
    }
    if (tid < 128) { mrow[tid] = -INFINITY; lrow[tid] = 0.f; }

    float oacc[2][4][4];
#pragma unroll
    for (int mi = 0; mi < 2; mi++)
#pragma unroll
        for (int nj = 0; nj < 4; nj++)
#pragma unroll
            for (int r = 0; r < 4; r++) oacc[mi][nj][r] = 0.f;

    const int nkt = S >> 6;
    for (int kt = 0; kt < nkt; kt++) {
        const int k0 = kt * 64;
        __syncthreads();
#pragma unroll
        for (int i = 0; i < 2; i++) {
            int idx = tid + i * 256;
            int r = idx >> 3, c8 = idx & 7;
            const __half* src = &qb[(size_t)(k0 + r) * 1536];
            *(uint4*)&Kh[r * FA_HPAD + c8 * 8] = *(const uint4*)&src[512 + c8 * 8];
            uint4 v = *(const uint4*)&src[1024 + c8 * 8];
            const __half* vh = (const __half*)&v;
#pragma unroll
            for (int j = 0; j < 8; j++)
                Vt[(c8 * 8 + j) * FA_HPAD + r] = vh[j];
        }
        __syncthreads();

        float sacc[2][4][4];
#pragma unroll
        for (int mi = 0; mi < 2; mi++)
#pragma unroll
            for (int nj = 0; nj < 4; nj++)
#pragma unroll
                for (int r = 0; r < 4; r++) sacc[mi][nj][r] = 0.f;
#pragma unroll
        for (int kc = 0; kc < 4; kc++) {
            uint32_t af[2][4];
#pragma unroll
            for (int mi = 0; mi < 2; mi++) {
                uint32_t ap = qhA + ((wm * 32 + mi * 16 + lrw + rowOffA) * FA_HPAD
                                     + kc * 16 + colOffA) * 2;
                LDM_X4(af[mi][0], af[mi][1], af[mi][2], af[mi][3], ap);
            }
            uint32_t bf[4][2];
#pragma unroll
            for (int njp = 0; njp < 2; njp++) {
                uint32_t bp = khA + ((wn * 32 + njp * 16 + lrw + rowOffB) * FA_HPAD
                                     + kc * 16 + colOffB) * 2;
                uint32_t r0, r1, r2, r3;
                LDM_X4(r0, r1, r2, r3, bp);
                bf[njp * 2][0]     = r0;
                bf[njp * 2][1]     = r1;
                bf[njp * 2 + 1][0] = r2;
                bf[njp * 2 + 1][1] = r3;
            }
#pragma unroll
            for (int mi = 0; mi < 2; mi++)
#pragma unroll
                for (int nj = 0; nj < 4; nj++)
                    MMA_F16(sacc[mi][nj], af[mi][0], af[mi][1], af[mi][2], af[mi][3],
                            bf[nj][0], bf[nj][1]);
        }
#pragma unroll
        for (int mi = 0; mi < 2; mi++) {
            int r = wm * 32 + mi * 16 + gid;
#pragma unroll
            for (int nj = 0; nj < 4; nj++) {
                int c = wn * 32 + nj * 8 + tid4 * 2;
                float am0 = amb[k0 + c], am1 = amb[k0 + c + 1];
                Ss[r * FA_SPAD + c]           = sacc[mi][nj][0] * 0.125f + am0;
                Ss[r * FA_SPAD + c + 1]       = sacc[mi][nj][1] * 0.125f + am1;
                Ss[(r + 8) * FA_SPAD + c]     = sacc[mi][nj][2] * 0.125f + am0;
                Ss[(r + 8) * FA_SPAD + c + 1] = sacc[mi][nj][3] * 0.125f + am1;
            }
        }
        __syncthreads();
        {
            int r = tid >> 1, hf = tid & 1;
            float* srow = Ss + r * FA_SPAD + hf * 32;
            __half* prow = Ph + r * FA_HPAD + hf * 32;
            float mx = -INFINITY;
#pragma unroll 8
            for (int j = 0; j < 32; j++) mx = fmaxf(mx, srow[j]);
            mx = fmaxf(mx, __shfl_xor_sync(0xffffffffu, mx, 1));
            float mold = mrow[r];
            float mnew = fmaxf(mold, mx);
            float sum = 0.f;
#pragma unroll 8
            for (int j = 0; j < 32; j++) {
                float pv = __expf(srow[j] - mnew);
                prow[j] = __float2half_rn(pv);
                sum += pv;
            }
            sum += __shfl_xor_sync(0xffffffffu, sum, 1);
            if (hf == 0) {
                float alpha = __expf(mold - mnew);
                lrow[r] = lrow[r] * alpha + sum;
                mrow[r] = mnew;
                arow[r] = alpha;
            }
        }
        __syncthreads();

        float al[2][2];
#pragma unroll
        for (int mi = 0; mi < 2; mi++) {
            int r = wm * 32 + mi * 16 + gid;
            al[mi][0] = arow[r];
            al[mi][1] = arow[r + 8];
        }
#pragma unroll
        for (int mi = 0; mi < 2; mi++)
#pragma unroll
            for (int nj = 0; nj < 4; nj++) {
                oacc[mi][nj][0] *= al[mi][0];
                oacc[mi][nj][1] *= al[mi][0];
                oacc[mi][nj][2] *= al[mi][1];
                oacc[mi][nj][3] *= al[mi][1];
            }
#pragma unroll
        for (int kc = 0; kc < 4; kc++) {
            uint32_t af[2][4];
#pragma unroll
            for (int mi = 0; mi < 2; mi++) {
                uint32_t ap = phA + ((wm * 32 + mi * 16 + lrw + rowOffA) * FA_HPAD
                                     + kc * 16 + colOffA) * 2;
                LDM_X4(af[mi][0], af[mi][1], af[mi][2], af[mi][3], ap);
            }
            uint32_t bf[4][2];
#pragma unroll
            for (int njp = 0; njp < 2; njp++) {
                uint32_t bp = vtA + ((wn * 32 + njp * 16 + lrw + rowOffB) * FA_HPAD
                                     + kc * 16 + colOffB) * 2;
                uint32_t r0, r1, r2, r3;
                LDM_X4(r0, r1, r2, r3, bp);
                bf[njp * 2][0]     = r0;
                bf[njp * 2][1]     = r1;
                bf[njp * 2 + 1][0] = r2;
                bf[njp * 2 + 1][1] = r3;
            }
#pragma unroll
            for (int mi = 0; mi < 2; mi++)
#pragma unroll
                for (int nj = 0; nj < 4; nj++)
                    MMA_F16(oacc[mi][nj], af[mi][0], af[mi][1], af[mi][2], af[mi][3],
                            bf[nj][0], bf[nj][1]);
        }
    }
#pragma unroll
    for (int mi = 0; mi < 2; mi++) {
        int r = wm * 32 + mi * 16 + gid;
        float inv0 = 1.f / lrow[r];
        float inv1 = 1.f / lrow[r + 8];
#pragma unroll
        for (int nj = 0; nj < 4; nj++) {
            int c = wn * 32 + nj * 8 + tid4 * 2;
            __half2* o0 = (__half2*)&ctx[(size_t)(b * S + q0 + r) * DD + h * 64 + c];
            __half2* o1 = (__half2*)&ctx[(size_t)(b * S + q0 + r + 8) * DD + h * 64 + c];
            *o0 = __floats2half2_rn(oacc[mi][nj][0] * inv0, oacc[mi][nj][1] * inv0);
            *o1 = __floats2half2_rn(oacc[mi][nj][2] * inv1, oacc[mi][nj][3] * inv1);
        }
    }
}

// ---------------- embed + positional (reference adds pos[b], not pos[t]) ----
__global__ __launch_bounds__(256) void embed_kernel(const int* __restrict__ tokens,
                                                    const float* __restrict__ emb,
                                                    float* __restrict__ x,
                                                    __half* __restrict__ xh)
{
    int i = blockIdx.x * 256 + threadIdx.x;
    if (i >= BB*TT*DD) return;
    int d  = i & (DD-1);
    int bt = i / DD;
    int b  = bt / TT;
    int tok = tokens[bt];
    int half = d >> 1;
    float den = __expf(-(float)(2*half) * (logf(10000.f) / (float)DD));
    float ang = (float)b * den;
    float posv = (d & 1) ? cosf(ang) : sinf(ang);
    float v = 2.f * emb[(size_t)tok*DD + d] + posv;
    x[i] = v;
    xh[i] = __float2half_rn(v);
}

__global__ __launch_bounds__(256) void mask_kernel(const int* __restrict__ lens,
                                                   float* __restrict__ am, int S)
{
    int i = blockIdx.x*256 + threadIdx.x;
    if (i >= BB*S) return;
    int b = i / S, t = i % S;
    am[i] = (t > lens[b]) ? -INFINITY : 0.f;
}

// ---- out = LN(resid + delta); 128 thr x float4; writes fp32 + fp16 ----
__global__ __launch_bounds__(128) void add_ln_kernel(const float* __restrict__ resid,
                                                     const float* __restrict__ delta,
                                                     const float* __restrict__ g,
                                                     const float* __restrict__ bb,
                                                     float* __restrict__ out,
                                                     __half* __restrict__ outh)
{
    size_t row = blockIdx.x;
    int t = threadIdx.x;
    int warp = t >> 5, lane = t & 31;
    __shared__ float red1[4], red2[4];

    float4 r4 = *(const float4*)&resid[row*DD + t*4];
    float4 d4 = *(const float4*)&delta[row*DD + t*4];
    float v0 = r4.x + d4.x, v1 = r4.y + d4.y, v2 = r4.z + d4.z, v3 = r4.w + d4.w;

    float s = v0 + v1 + v2 + v3;
#pragma unroll
    for (int o = 16; o > 0; o >>= 1) s += __shfl_xor_sync(0xffffffffu, s, o);
    if (lane == 0) red1[warp] = s;
    __syncthreads();
    float mean = (red1[0] + red1[1] + red1[2] + red1[3]) * (1.f/DD);

    float e0 = v0 - mean, e1 = v1 - mean, e2 = v2 - mean, e3 = v3 - mean;
    float q = e0*e0 + e1*e1 + e2*e2 + e3*e3;
#pragma unroll
    for (int o = 16; o > 0; o >>= 1) q += __shfl_xor_sync(0xffffffffu, q, o);
    if (lane == 0) red2[warp] = q;
    __syncthreads();
    float var = (red2[0] + red2[1] + red2[2] + red2[3]) * (1.f/DD);
    float sc = rsqrtf(var + 1e-5f);

    float4 g4 = *(const float4*)&g[t*4];
    float4 b4 = *(const float4*)&bb[t*4];
    float o0 = e0*sc*g4.x + b4.x;
    float o1 = e1*sc*g4.y + b4.y;
    float o2 = e2*sc*g4.z + b4.z;
    float o3 = e3*sc*g4.w + b4.w;
    *(float4*)&out[row*DD + t*4] = make_float4(o0, o1, o2, o3);
    __half2 h0 = __floats2half2_rn(o0, o1);
    __half2 h1 = __floats2half2_rn(o2, o3);
    *(uint2*)&outh[row*DD + t*4] = make_uint2(*(uint32_t*)&h0, *(uint32_t*)&h1);
}

__global__ void cumsum_kernel(const int* __restrict__ dur, int* __restrict__ cums)
{
    int b = blockIdx.x;
    if (threadIdx.x == 0) {
        int s = 0;
        for (int t = 0; t < TT; t++) { s += dur[b*TT + t]; cums[b*TT + t] = s; }
    }
}

__global__ __launch_bounds__(256) void regulate_kernel(const float* __restrict__ enc,
                                                       const int* __restrict__ cums,
                                                       const int* __restrict__ mellen,
                                                       float* __restrict__ dec_in,
                                                       __half* __restrict__ dec_inh)
{
    int bf = blockIdx.x;
    int b = bf / MELN, f = bf % MELN;
    const int* c = cums + b*TT;
    int lo = 0, hi = TT;
    while (lo < hi) { int mid = (lo + hi) >> 1; if (c[mid] <= f) lo = mid + 1; else hi = mid; }
    int idx = lo; if (idx > TT-1) idx = TT-1;
    float keep = (f <= mellen[b]) ? 1.f : 0.f;
    for (int d = threadIdx.x; d < DD; d += 256) {
        float v = enc[(size_t)(b*TT + idx)*DD + d] * keep;
        dec_in[(size_t)bf*DD + d]  = v;
        dec_inh[(size_t)bf*DD + d] = __float2half_rn(v);
    }
}

// =============================== host side ===============================
struct Ptrs {
    float *x, *ctx, *t1, *h2, *enc, *am, *am2;
    __half *xh, *qkvh, *ctxh, *hh, *wh, *whOut;
    int *cums;
};

static void get_ptrs(Ptrs& p)
{
    cudaGetSymbolAddress((void**)&p.x,     g_x);
    cudaGetSymbolAddress((void**)&p.xh,    g_xh);
    cudaGetSymbolAddress((void**)&p.qkvh,  g_qkvh);
    cudaGetSymbolAddress((void**)&p.ctx,   g_ctx);
    cudaGetSymbolAddress((void**)&p.ctxh,  g_ctxh);
    cudaGetSymbolAddress((void**)&p.t1,    g_t1);
    cudaGetSymbolAddress((void**)&p.hh,    g_hh);
    cudaGetSymbolAddress((void**)&p.h2,    g_h2);
    cudaGetSymbolAddress((void**)&p.enc,   g_enc);
    cudaGetSymbolAddress((void**)&p.am,    g_am);
    cudaGetSymbolAddress((void**)&p.am2,   g_am2);
    cudaGetSymbolAddress((void**)&p.wh,    g_wh);
    cudaGetSymbolAddress((void**)&p.whOut, g_whOut);
    cudaGetSymbolAddress((void**)&p.cums,  g_cums);
}

static void run_layer(Ptrs& p, int S, int sLog, const float* am, const __half* whl,
                      const float* bqkv, const float* bo,
                      const float* ln1g, const float* ln1b,
                      const float* c1b,  const float* c2b,
                      const float* ln2g, const float* ln2b)
{
    const int M = BB * S;
    const bool small = (S == TT);

    if (small)
        gemm_h<2><<<dim3(12, M/64), 256, H_SMEM_64>>>(p.xh, whl + WT_QKV, bqkv,
                                                      nullptr, p.qkvh,
                                                      M, 3*DD, DD, DD, sLog, 0, 0, 1, 0);
    else
        gemm_h<4><<<dim3(12, M/128), 256, H_SMEM_128>>>(p.xh, whl + WT_QKV, bqkv,
                                                        nullptr, p.qkvh,
                                                        M, 3*DD, DD, DD, sLog, 0, 0, 1, 0);

    flash_attn<<<dim3(S/128, BB*HH), 256, FA_SMEM_BYTES>>>(p.qkvh, am, p.ctxh, S);

    if (small)
        gemm_h<2><<<dim3(4, M/64), 256, H_SMEM_64>>>(p.ctxh, whl + WT_WO, bo,
                                                     p.t1, nullptr,
                                                     M, DD, DD, DD, sLog, 0, 0, 0, 0);
    else
        gemm_h<4><<<dim3(4, M/128), 256, H_SMEM_128>>>(p.ctxh, whl + WT_WO, bo,
                                                       p.t1, nullptr,
                                                       M, DD, DD, DD, sLog, 0, 0, 0, 0);

    add_ln_kernel<<<M, 128>>>(p.x, p.t1, ln1g, ln1b, p.ctx, p.xh);

    gemm_h<4><<<dim3(16, M/128), 256, H_SMEM_128>>>(p.xh, whl + WT_C1, c1b,
                                                    nullptr, p.hh,
                                                    M, INTERN, 3*DD, DD, sLog, 1, 1, 1, 0);
    if (small)
        gemm_h<2><<<dim3(4, M/64), 256, H_SMEM_64>>>(p.hh, whl + WT_C2, c2b,
                                                     p.h2, nullptr,
                                                     M, DD, 3*INTERN, INTERN, sLog, 1, 0, 0, 0);
    else
        gemm_h<4><<<dim3(4, M/128), 256, H_SMEM_128>>>(p.hh, whl + WT_C2, c2b,
                                                       p.h2, nullptr,
                                                       M, DD, 3*INTERN, INTERN, sLog, 1, 0, 0, 0);

    add_ln_kernel<<<M, 128>>>(p.ctx, p.h2, ln2g, ln2b, p.x, p.xh);
}

extern "C" void kernel_launch(void* const* d_in, const int* in_sizes, int n_in,
                              void* d_out, int out_size)
{
    const int*   tokens        = (const int*)  d_in[0];
    const int*   token_lengths = (const int*)  d_in[1];
    const int*   melspec_len   = (const int*)  d_in[2];
    const int*   durations     = (const int*)  d_in[3];
    const float* emb           = (const float*)d_in[5];
    const float* ew[12]; for (int i = 0; i < 12; i++) ew[i] = (const float*)d_in[6 + i];
    const float* dw[12]; for (int i = 0; i < 12; i++) dw[i] = (const float*)d_in[18 + i];
    const float* out_w         = (const float*)d_in[30];
    const float* out_b         = (const float*)d_in[31];

    cudaFuncSetAttribute(flash_attn, cudaFuncAttributeMaxDynamicSharedMemorySize,
                         FA_SMEM_BYTES);
    cudaFuncSetAttribute(gemm_h<4>, cudaFuncAttributeMaxDynamicSharedMemorySize,
                         H_SMEM_128);
    cudaFuncSetAttribute(gemm_h<2>, cudaFuncAttributeMaxDynamicSharedMemorySize,
                         H_SMEM_64);

    Ptrs p; get_ptrs(p);

    // ---- weight transpose + fp16 convert (batched: blockIdx.z = layer) ----
    for (int half = 0; half < 2; half++) {
        const float* const* w = (half == 0) ? ew : dw;
        __half* whb = p.wh + (size_t)half * LLAY * WT_LAYER;
        transpose_wh<<<dim3(16, 48, LLAY), 256>>>(w[0], whb + WT_QKV, DD, 3*DD,
                                                  (size_t)DD*3*DD, WT_LAYER);
        transpose_wh<<<dim3(16, 16, LLAY), 256>>>(w[2], whb + WT_WO, DD, DD,
                                                  (size_t)DD*DD, WT_LAYER);
        transpose_wh<<<dim3(48, 64, LLAY), 256>>>(w[6], whb + WT_C1, 3*DD, INTERN,
                                                  (size_t)3*DD*INTERN, WT_LAYER);
        transpose_wh<<<dim3(192, 16, LLAY), 256>>>(w[8], whb + WT_C2, 3*INTERN, DD,
                                                   (size_t)3*INTERN*DD, WT_LAYER);
    }
    transpose_wh<<<dim3(16, 3, 1), 256>>>(out_w, p.whOut, DD, OUTC, 0, 0);

    // ---- embed + positional + encoder mask ----
    embed_kernel<<<(BB*TT*DD + 255)/256, 256>>>(tokens, emb, p.x, p.xh);
    mask_kernel<<<(BB*TT + 255)/256, 256>>>(token_lengths, p.am, TT);

    // ---- encoder stack (S = TT) ----
    for (int l = 0; l < LLAY; l++) {
        run_layer(p, TT, 8, p.am, p.wh + (size_t)l * WT_LAYER,
                  ew[1] + (size_t)l*3*DD,  ew[3] + (size_t)l*DD,
                  ew[4] + (size_t)l*DD,    ew[5] + (size_t)l*DD,
                  ew[7] + (size_t)l*INTERN, ew[9] + (size_t)l*DD,
                  ew[10] + (size_t)l*DD,   ew[11] + (size_t)l*DD);
    }

    // ---- length regulator ----
    cudaMemcpyAsync(p.enc, p.x, (size_t)BB*TT*DD*sizeof(float), cudaMemcpyDeviceToDevice);
    cumsum_kernel<<<BB, 32>>>(durations, p.cums);
    regulate_kernel<<<BB*MELN, 256>>>(p.enc, p.cums, melspec_len, p.x, p.xh);
    mask_kernel<<<(BB*MELN + 255)/256, 256>>>(melspec_len, p.am2, MELN);

    // ---- decoder stack (S = MELN) ----
    for (int l = 0; l < LLAY; l++) {
        run_layer(p, MELN, 10, p.am2, p.wh + (size_t)(LLAY + l) * WT_LAYER,
                  dw[1] + (size_t)l*3*DD,  dw[3] + (size_t)l*DD,
                  dw[4] + (size_t)l*DD,    dw[5] + (size_t)l*DD,
                  dw[7] + (size_t)l*INTERN, dw[9] + (size_t)l*DD,
                  dw[10] + (size_t)l*DD,   dw[11] + (size_t)l*DD);
    }

    // ---- output projection fused with transpose: writes (b, o, f) ----
    gemm_h<2><<<dim3(1, BB*MELN/64), 256, H_SMEM_64>>>(p.xh, p.whOut, out_b,
                                                       (float*)d_out, nullptr,
                                                       BB*MELN, OUTC, DD, DD, 10,
                                                       0, 0, 0, 1);
}

// round 16
// speedup vs baseline: 1.4672x; 1.0014x over previous
#include <cuda_runtime.h>
#include <cuda_fp16.h>
#include <math.h>
#include <stdint.h>

// ---------------- problem constants ----------------
#define BB    16
#define TT    256
#define MELN  1024
#define DD    512
#define HH    8
#define DHD   64
#define LLAY  4
#define INTERN 2048
#define OUTC  80

// ---------------- scratch (device globals; no allocation allowed) ----------
__device__ float  g_x   [(size_t)BB*MELN*DD];
__device__ __half g_xh  [(size_t)BB*MELN*DD];
__device__ __half g_qkvh[(size_t)BB*MELN*3*DD];
__device__ float  g_ctx [(size_t)BB*MELN*DD];
__device__ __half g_ctxh[(size_t)BB*MELN*DD];
__device__ float  g_t1  [(size_t)BB*MELN*DD];
__device__ __half g_hh  [(size_t)BB*MELN*INTERN];
__device__ float  g_h2  [(size_t)BB*MELN*DD];
__device__ float  g_enc [(size_t)BB*TT*DD];
__device__ float  g_am  [BB*TT];
__device__ float  g_am2 [BB*MELN];
__device__ int    g_cums[BB*TT];
#define WT_QKV   0
#define WT_WO    786432
#define WT_C1    1048576
#define WT_C2    4194304
#define WT_LAYER 7340032
__device__ __half g_wh   [(size_t)WT_LAYER * 8];
__device__ __half g_whOut[OUTC * DD];

// ---------------- small helpers ----------------
__device__ __forceinline__ uint32_t smem_u32(const void* p) {
    uint32_t a;
    asm("{ .reg .u64 t; cvta.to.shared.u64 t, %1; cvt.u32.u64 %0, t; }" : "=r"(a) : "l"(p));
    return a;
}

#define MMA_F16(acc, a0,a1,a2,a3, b0,b1)                                      \
    asm volatile("mma.sync.aligned.m16n8k16.row.col.f32.f16.f16.f32 "         \
                 "{%0,%1,%2,%3},{%4,%5,%6,%7},{%8,%9},{%0,%1,%2,%3};"         \
                 : "+f"(acc[0]), "+f"(acc[1]), "+f"(acc[2]), "+f"(acc[3])     \
                 : "r"(a0), "r"(a1), "r"(a2), "r"(a3), "r"(b0), "r"(b1))

#define LDM_X4(r0,r1,r2,r3, addr)                                             \
    asm volatile("ldmatrix.sync.aligned.m8n8.x4.shared.b16 {%0,%1,%2,%3}, [%4];" \
                 : "=r"(r0), "=r"(r1), "=r"(r2), "=r"(r3) : "r"(addr))

#define CP16(dst, src, sz)                                                    \
    asm volatile("cp.async.cg.shared.global [%0], [%1], 16, %2;"              \
                 :: "r"(dst), "l"(src), "r"(sz) : "memory")
#define CP_COMMIT()  asm volatile("cp.async.commit_group;" ::: "memory")
#define CP_WAIT2()   asm volatile("cp.async.wait_group 2;" ::: "memory")

// ===== weight transpose + fp16 convert, enc+dec batched (z in [0, 2*L)) ====
__global__ __launch_bounds__(256) void transpose_wh2(const float* __restrict__ W0,
                                                     const float* __restrict__ W1,
                                                     __half* __restrict__ WH,
                                                     int K, int N,
                                                     size_t wStride, size_t whStride)
{
    int z = blockIdx.z;
    const float* Wl = ((z < LLAY) ? W0 : W1) + (size_t)(z & (LLAY-1)) * wStride;
    __half* WHl = WH + (size_t)z * whStride;
    __shared__ float t[32][33];
    int k0 = blockIdx.x * 32, n0 = blockIdx.y * 32;
    int tx = threadIdx.x & 31, ty = threadIdx.x >> 5;
#pragma unroll
    for (int i = 0; i < 4; i++) {
        int r = ty + i * 8;
        t[r][tx] = (n0 + tx < N) ? Wl[(size_t)(k0 + r) * N + n0 + tx] : 0.f;
    }
    __syncthreads();
#pragma unroll
    for (int i = 0; i < 4; i++) {
        int r = ty + i * 8;
        if (n0 + r < N)
            WHl[(size_t)(n0 + r) * K + k0 + tx] = __float2half_rn(t[tx][r]);
    }
}

__global__ __launch_bounds__(256) void transpose_whS(const float* __restrict__ W,
                                                     __half* __restrict__ WH,
                                                     int K, int N)
{
    __shared__ float t[32][33];
    int k0 = blockIdx.x * 32, n0 = blockIdx.y * 32;
    int tx = threadIdx.x & 31, ty = threadIdx.x >> 5;
#pragma unroll
    for (int i = 0; i < 4; i++) {
        int r = ty + i * 8;
        t[r][tx] = (n0 + tx < N) ? W[(size_t)(k0 + r) * N + n0 + tx] : 0.f;
    }
    __syncthreads();
#pragma unroll
    for (int i = 0; i < 4; i++) {
        int r = ty + i * 8;
        if (n0 + r < N)
            WH[(size_t)(n0 + r) * K + k0 + tx] = __float2half_rn(t[tx][r]);
    }
}

// ========== cp.async pipelined fp16 GEMM (row layout, 4-stage) =============
#define H_STRIDE 40
#define HB_HALVES (128*H_STRIDE)

template<int MI>
__global__ __launch_bounds__(256, 2) void gemm_h(
    const __half* __restrict__ A, const __half* __restrict__ WT,
    const float* __restrict__ bias, float* __restrict__ C32,
    __half* __restrict__ C16,
    int M, int N, int Ktot, int Kin, int sLog, int conv, int relu,
    int halfOut, int transOut)
{
    constexpr int BM = MI * 32;
    constexpr int HA_HALVES = BM * H_STRIDE;
    constexpr int STAGE_BYTES = (HA_HALVES + HB_HALVES) * 2;

    extern __shared__ char sm[];
    const uint32_t sbase = smem_u32(sm);

    const int tid  = threadIdx.x;
    const int warp = tid >> 5, lane = tid & 31;
    const int gid  = lane >> 2, tid4 = lane & 3;
    const int wm   = warp & 1,  wn   = warp >> 1;
    const int bm   = blockIdx.y * BM;
    const int bn   = blockIdx.x * 128;
    const int S    = 1 << sLog;
    const int nst  = Ktot / 32;

    const int lrow = lane & 7;
    const int lsel = lane >> 3;
    const int rowOffA = (lsel & 1) * 8;
    const int colOffA = (lsel >> 1) * 8;
    const int rowOffB = (lsel >> 1) * 8;
    const int colOffB = (lsel & 1) * 8;

    float acc[MI][4][4];
#pragma unroll
    for (int i = 0; i < MI; i++)
#pragma unroll
        for (int j = 0; j < 4; j++)
#pragma unroll
            for (int r = 0; r < 4; r++) acc[i][j][r] = 0.f;

    auto issue_stage = [&](int stg) {
        const int k0    = stg * 32;
        const int tap   = conv ? (k0 / Kin) : 0;
        const int kcol  = k0 - tap * Kin;
        const int shift = conv ? (tap - 1) : 0;
        const uint32_t aB = sbase + (stg & 3) * STAGE_BYTES;
        const uint32_t bB = aB + HA_HALVES * 2;
#pragma unroll
        for (int i = 0; i < BM / 64; i++) {
            int flat = tid + i * 256;
            int row = flat >> 2, cq = flat & 3;
            int gm = bm + row;
            int b = gm >> sLog, l = gm & (S - 1);
            int src = l + shift;
            uint32_t sz = (src >= 0 && src < S) ? 16u : 0u;
            int srcc = (src >= 0 && src < S) ? src : 0;
            const __half* gp = A + (size_t)(((size_t)b << sLog) + srcc) * Kin + kcol + cq * 8;
            CP16(aB + (row * H_STRIDE + cq * 8) * 2, gp, sz);
        }
#pragma unroll
        for (int i = 0; i < 2; i++) {
            int flat = tid + i * 256;
            int nr = flat >> 2, cq = flat & 3;
            int gn = bn + nr;
            uint32_t sz = (gn < N) ? 16u : 0u;
            int gnc = (gn < N) ? gn : (N - 1);
            const __half* gp = WT + (size_t)gnc * Ktot + k0 + cq * 8;
            CP16(bB + (nr * H_STRIDE + cq * 8) * 2, gp, sz);
        }
    };

    auto compute = [&](int stg) {
        const uint32_t aB = sbase + (stg & 3) * STAGE_BYTES;
        const uint32_t bB = aB + HA_HALVES * 2;
#pragma unroll
        for (int c = 0; c < 2; c++) {
            uint32_t af[MI][4];
#pragma unroll
            for (int mi = 0; mi < MI; mi++) {
                uint32_t ap = aB + ((wm * (MI*16) + mi * 16 + lrow + rowOffA) * H_STRIDE
                                    + c * 16 + colOffA) * 2;
                LDM_X4(af[mi][0], af[mi][1], af[mi][2], af[mi][3], ap);
            }
            uint32_t bf[4][2];
#pragma unroll
            for (int njp = 0; njp < 2; njp++) {
                uint32_t bp = bB + ((wn * 32 + njp * 16 + lrow + rowOffB) * H_STRIDE
                                    + c * 16 + colOffB) * 2;
                uint32_t r0, r1, r2, r3;
                LDM_X4(r0, r1, r2, r3, bp);
                bf[njp * 2][0]     = r0;
                bf[njp * 2][1]     = r1;
                bf[njp * 2 + 1][0] = r2;
                bf[njp * 2 + 1][1] = r3;
            }
#pragma unroll
            for (int mi = 0; mi < MI; mi++)
#pragma unroll
                for (int nj = 0; nj < 4; nj++)
                    MMA_F16(acc[mi][nj], af[mi][0], af[mi][1], af[mi][2], af[mi][3],
                            bf[nj][0], bf[nj][1]);
        }
    };

    issue_stage(0); CP_COMMIT();
    issue_stage(1); CP_COMMIT();
    issue_stage(2); CP_COMMIT();
    for (int s = 0; s < nst; s++) {
        CP_WAIT2();
        __syncthreads();
        if (s + 3 < nst) issue_stage(s + 3);
        CP_COMMIT();
        compute(s);
    }

#pragma unroll
    for (int mi = 0; mi < MI; mi++) {
        int gm0 = bm + wm * (MI*16) + mi * 16 + gid;
#pragma unroll
        for (int nj = 0; nj < 4; nj++) {
            int gn = bn + wn * 32 + nj * 8 + tid4 * 2;
            float b0 = (gn < N) ? bias[gn] : 0.f;
            float b1 = (gn + 1 < N) ? bias[gn + 1] : 0.f;
            float v00 = acc[mi][nj][0] + b0;
            float v01 = acc[mi][nj][1] + b1;
            float v10 = acc[mi][nj][2] + b0;
            float v11 = acc[mi][nj][3] + b1;
            if (relu) {
                v00 = fmaxf(v00, 0.f); v01 = fmaxf(v01, 0.f);
                v10 = fmaxf(v10, 0.f); v11 = fmaxf(v11, 0.f);
            }
            if (transOut) {
                int b0i = gm0 >> sLog, f0 = gm0 & (S - 1);
                int b1i = (gm0 + 8) >> sLog, f1 = (gm0 + 8) & (S - 1);
                if (gn < N) {
                    C32[((size_t)b0i * N + gn) * S + f0] = v00;
                    C32[((size_t)b1i * N + gn) * S + f1] = v10;
                }
                if (gn + 1 < N) {
                    C32[((size_t)b0i * N + gn + 1) * S + f0] = v01;
                    C32[((size_t)b1i * N + gn + 1) * S + f1] = v11;
                }
            } else if (halfOut) {
                *(__half2*)&C16[(size_t)gm0 * N + gn]       = __floats2half2_rn(v00, v01);
                *(__half2*)&C16[(size_t)(gm0 + 8) * N + gn] = __floats2half2_rn(v10, v11);
            } else {
                C32[(size_t)gm0 * N + gn]           = v00;
                C32[(size_t)gm0 * N + gn + 1]       = v01;
                C32[(size_t)(gm0 + 8) * N + gn]     = v10;
                C32[(size_t)(gm0 + 8) * N + gn + 1] = v11;
            }
        }
    }
}

#define H_SMEM_128 (4 * ((128*H_STRIDE + HB_HALVES) * 2))   // 81920
#define H_SMEM_64  (4 * (( 64*H_STRIDE + HB_HALVES) * 2))   // 61440

// ============== fused flash attention (full fp16 mma path) ==============
#define FA_SPAD 68
#define FA_HPAD 72
#define FA_F32_FLOATS (128*FA_SPAD + 3*128)
#define FA_SMEM_BYTES (FA_F32_FLOATS*4 + (128+64+64+128)*FA_HPAD*2)

__global__ __launch_bounds__(256) void flash_attn(const __half* __restrict__ qkv,
                                                  const float* __restrict__ am,
                                                  __half* __restrict__ ctx, int S)
{
    extern __shared__ float smf[];
    float* Ss   = smf;
    float* mrow = Ss + 128*FA_SPAD;
    float* lrow = mrow + 128;
    float* arow = lrow + 128;
    __half* Qh = (__half*)(arow + 128);
    __half* Kh = Qh + 128*FA_HPAD;
    __half* Vt = Kh + 64*FA_HPAD;
    __half* Ph = Vt + 64*FA_HPAD;

    const uint32_t qhA = smem_u32(Qh);
    const uint32_t khA = smem_u32(Kh);
    const uint32_t vtA = smem_u32(Vt);
    const uint32_t phA = smem_u32(Ph);

    const int tid  = threadIdx.x;
    const int warp = tid >> 5, lane = tid & 31;
    const int gid  = lane >> 2, tid4 = lane & 3;
    const int wm   = warp & 3, wn = warp >> 2;
    const int bh   = blockIdx.y;
    const int b    = bh >> 3, h = bh & 7;
    const int q0   = blockIdx.x * 128;
    const float* amb = am + b * S;
    const __half* qb = qkv + (size_t)(b * S) * 1536 + h * 64;

    const int lrw  = lane & 7;
    const int lsel = lane >> 3;
    const int rowOffA = (lsel & 1) * 8;
    const int colOffA = (lsel >> 1) * 8;
    const int rowOffB = (lsel >> 1) * 8;
    const int colOffB = (lsel & 1) * 8;

#pragma unroll
    for (int i = 0; i < 4; i++) {
        int idx = tid + i * 256;
        int r = idx >> 3, c8 = idx & 7;
        *(uint4*)&Qh[r * FA_HPAD + c8 * 8] =
            *(const uint4*)&qb[(size_t)(q0 + r) * 1536 + c8 * 8];
    }
    if (tid < 128) { mrow[tid] = -INFINITY; lrow[tid] = 0.f; }

    float oacc[2][4][4];
#pragma unroll
    for (int mi = 0; mi < 2; mi++)
#pragma unroll
        for (int nj = 0; nj < 4; nj++)
#pragma unroll
            for (int r = 0; r < 4; r++) oacc[mi][nj][r] = 0.f;

    const int nkt = S >> 6;
    for (int kt = 0; kt < nkt; kt++) {
        const int k0 = kt * 64;
        __syncthreads();
#pragma unroll
        for (int i = 0; i < 2; i++) {
            int idx = tid + i * 256;
            int r = idx >> 3, c8 = idx & 7;
            const __half* src = &qb[(size_t)(k0 + r) * 1536];
            *(uint4*)&Kh[r * FA_HPAD + c8 * 8] = *(const uint4*)&src[512 + c8 * 8];
            uint4 v = *(const uint4*)&src[1024 + c8 * 8];
            const __half* vh = (const __half*)&v;
#pragma unroll
            for (int j = 0; j < 8; j++)
                Vt[(c8 * 8 + j) * FA_HPAD + r] = vh[j];
        }
        __syncthreads();

        float sacc[2][4][4];
#pragma unroll
        for (int mi = 0; mi < 2; mi++)
#pragma unroll
            for (int nj = 0; nj < 4; nj++)
#pragma unroll
                for (int r = 0; r < 4; r++) sacc[mi][nj][r] = 0.f;
#pragma unroll
        for (int kc = 0; kc < 4; kc++) {
            uint32_t af[2][4];
#pragma unroll
            for (int mi = 0; mi < 2; mi++) {
                uint32_t ap = qhA + ((wm * 32 + mi * 16 + lrw + rowOffA) * FA_HPAD
                                     + kc * 16 + colOffA) * 2;
                LDM_X4(af[mi][0], af[mi][1], af[mi][2], af[mi][3], ap);
            }
            uint32_t bf[4][2];
#pragma unroll
            for (int njp = 0; njp < 2; njp++) {
                uint32_t bp = khA + ((wn * 32 + njp * 16 + lrw + rowOffB) * FA_HPAD
                                     + kc * 16 + colOffB) * 2;
                uint32_t r0, r1, r2, r3;
                LDM_X4(r0, r1, r2, r3, bp);
                bf[njp * 2][0]     = r0;
                bf[njp * 2][1]     = r1;
                bf[njp * 2 + 1][0] = r2;
                bf[njp * 2 + 1][1] = r3;
            }
#pragma unroll
            for (int mi = 0; mi < 2; mi++)
#pragma unroll
                for (int nj = 0; nj < 4; nj++)
                    MMA_F16(sacc[mi][nj], af[mi][0], af[mi][1], af[mi][2], af[mi][3],
                            bf[nj][0], bf[nj][1]);
        }
#pragma unroll
        for (int mi = 0; mi < 2; mi++) {
            int r = wm * 32 + mi * 16 + gid;
#pragma unroll
            for (int nj = 0; nj < 4; nj++) {
                int c = wn * 32 + nj * 8 + tid4 * 2;
                float am0 = amb[k0 + c], am1 = amb[k0 + c + 1];
                Ss[r * FA_SPAD + c]           = sacc[mi][nj][0] * 0.125f + am0;
                Ss[r * FA_SPAD + c + 1]       = sacc[mi][nj][1] * 0.125f + am1;
                Ss[(r + 8) * FA_SPAD + c]     = sacc[mi][nj][2] * 0.125f + am0;
                Ss[(r + 8) * FA_SPAD + c + 1] = sacc[mi][nj][3] * 0.125f + am1;
            }
        }
        __syncthreads();
        {
            int r = tid >> 1, hf = tid & 1;
            float* srow = Ss + r * FA_SPAD + hf * 32;
            __half* prow = Ph + r * FA_HPAD + hf * 32;
            float mx = -INFINITY;
#pragma unroll 8
            for (int j = 0; j < 32; j++) mx = fmaxf(mx, srow[j]);
            mx = fmaxf(mx, __shfl_xor_sync(0xffffffffu, mx, 1));
            float mold = mrow[r];
            float mnew = fmaxf(mold, mx);
            float sum = 0.f;
#pragma unroll 8
            for (int j = 0; j < 32; j++) {
                float pv = __expf(srow[j] - mnew);
                prow[j] = __float2half_rn(pv);
                sum += pv;
            }
            sum += __shfl_xor_sync(0xffffffffu, sum, 1);
            if (hf == 0) {
                float alpha = __expf(mold - mnew);
                lrow[r] = lrow[r] * alpha + sum;
                mrow[r] = mnew;
                arow[r] = alpha;
            }
        }
        __syncthreads();

        float al[2][2];
#pragma unroll
        for (int mi = 0; mi < 2; mi++) {
            int r = wm * 32 + mi * 16 + gid;
            al[mi][0] = arow[r];
            al[mi][1] = arow[r + 8];
        }
#pragma unroll
        for (int mi = 0; mi < 2; mi++)
#pragma unroll
            for (int nj = 0; nj < 4; nj++) {
                oacc[mi][nj][0] *= al[mi][0];
                oacc[mi][nj][1] *= al[mi][0];
                oacc[mi][nj][2] *= al[mi][1];
                oacc[mi][nj][3] *= al[mi][1];
            }
#pragma unroll
        for (int kc = 0; kc < 4; kc++) {
            uint32_t af[2][4];
#pragma unroll
            for (int mi = 0; mi < 2; mi++) {
                uint32_t ap = phA + ((wm * 32 + mi * 16 + lrw + rowOffA) * FA_HPAD
                                     + kc * 16 + colOffA) * 2;
                LDM_X4(af[mi][0], af[mi][1], af[mi][2], af[mi][3], ap);
            }
            uint32_t bf[4][2];
#pragma unroll
            for (int njp = 0; njp < 2; njp++) {
                uint32_t bp = vtA + ((wn * 32 + njp * 16 + lrw + rowOffB) * FA_HPAD
                                     + kc * 16 + colOffB) * 2;
                uint32_t r0, r1, r2, r3;
                LDM_X4(r0, r1, r2, r3, bp);
                bf[njp * 2][0]     = r0;
                bf[njp * 2][1]     = r1;
                bf[njp * 2 + 1][0] = r2;
                bf[njp * 2 + 1][1] = r3;
            }
#pragma unroll
            for (int mi = 0; mi < 2; mi++)
#pragma unroll
                for (int nj = 0; nj < 4; nj++)
                    MMA_F16(oacc[mi][nj], af[mi][0], af[mi][1], af[mi][2], af[mi][3],
                            bf[nj][0], bf[nj][1]);
        }
    }
#pragma unroll
    for (int mi = 0; mi < 2; mi++) {
        int r = wm * 32 + mi * 16 + gid;
        float inv0 = 1.f / lrow[r];
        float inv1 = 1.f / lrow[r + 8];
#pragma unroll
        for (int nj = 0; nj < 4; nj++) {
            int c = wn * 32 + nj * 8 + tid4 * 2;
            __half2* o0 = (__half2*)&ctx[(size_t)(b * S + q0 + r) * DD + h * 64 + c];
            __half2* o1 = (__half2*)&ctx[(size_t)(b * S + q0 + r + 8) * DD + h * 64 + c];
            *o0 = __floats2half2_rn(oacc[mi][nj][0] * inv0, oacc[mi][nj][1] * inv0);
            *o1 = __floats2half2_rn(oacc[mi][nj][2] * inv1, oacc[mi][nj][3] * inv1);
        }
    }
}

// ---------------- embed + positional (reference adds pos[b], not pos[t]) ----
__global__ __launch_bounds__(256) void embed_kernel(const int* __restrict__ tokens,
                                                    const float* __restrict__ emb,
                                                    float* __restrict__ x,
                                                    __half* __restrict__ xh)
{
    int i = blockIdx.x * 256 + threadIdx.x;
    if (i >= BB*TT*DD) return;
    int d  = i & (DD-1);
    int bt = i / DD;
    int b  = bt / TT;
    int tok = tokens[bt];
    int half = d >> 1;
    float den = __expf(-(float)(2*half) * (logf(10000.f) / (float)DD));
    float ang = (float)b * den;
    float posv = (d & 1) ? cosf(ang) : sinf(ang);
    float v = 2.f * emb[(size_t)tok*DD + d] + posv;
    x[i] = v;
    xh[i] = __float2half_rn(v);
}

__global__ __launch_bounds__(256) void mask_kernel(const int* __restrict__ lens,
                                                   float* __restrict__ am, int S)
{
    int i = blockIdx.x*256 + threadIdx.x;
    if (i >= BB*S) return;
    int b = i / S, t = i % S;
    am[i] = (t > lens[b]) ? -INFINITY : 0.f;
}

// ---- LN(resid + delta): 2 rows per 256-thread block, float4 per thread ----
__global__ __launch_bounds__(256) void add_ln_kernel(const float* __restrict__ resid,
                                                     const float* __restrict__ delta,
                                                     const float* __restrict__ g,
                                                     const float* __restrict__ bb,
                                                     float* __restrict__ out,
                                                     __half* __restrict__ outh)
{
    int half = threadIdx.x >> 7;            // 0 or 1: which row of the pair
    int t    = threadIdx.x & 127;
    size_t row = (size_t)blockIdx.x * 2 + half;
    int warp = t >> 5, lane = t & 31;
    __shared__ float red1[2][4], red2[2][4];

    float4 r4 = *(const float4*)&resid[row*DD + t*4];
    float4 d4 = *(const float4*)&delta[row*DD + t*4];
    float v0 = r4.x + d4.x, v1 = r4.y + d4.y, v2 = r4.z + d4.z, v3 = r4.w + d4.w;

    float s = v0 + v1 + v2 + v3;
#pragma unroll
    for (int o = 16; o > 0; o >>= 1) s += __shfl_xor_sync(0xffffffffu, s, o);
    if (lane == 0) red1[half][warp] = s;
    __syncthreads();
    float mean = (red1[half][0] + red1[half][1] + red1[half][2] + red1[half][3]) * (1.f/DD);

    float e0 = v0 - mean, e1 = v1 - mean, e2 = v2 - mean, e3 = v3 - mean;
    float q = e0*e0 + e1*e1 + e2*e2 + e3*e3;
#pragma unroll
    for (int o = 16; o > 0; o >>= 1) q += __shfl_xor_sync(0xffffffffu, q, o);
    if (lane == 0) red2[half][warp] = q;
    __syncthreads();
    float var = (red2[half][0] + red2[half][1] + red2[half][2] + red2[half][3]) * (1.f/DD);
    float sc = rsqrtf(var + 1e-5f);

    float4 g4 = *(const float4*)&g[t*4];
    float4 b4 = *(const float4*)&bb[t*4];
    float o0 = e0*sc*g4.x + b4.x;
    float o1 = e1*sc*g4.y + b4.y;
    float o2 = e2*sc*g4.z + b4.z;
    float o3 = e3*sc*g4.w + b4.w;
    *(float4*)&out[row*DD + t*4] = make_float4(o0, o1, o2, o3);
    __half2 h0 = __floats2half2_rn(o0, o1);
    __half2 h1 = __floats2half2_rn(o2, o3);
    *(uint2*)&outh[row*DD + t*4] = make_uint2(*(uint32_t*)&h0, *(uint32_t*)&h1);
}

__global__ void cumsum_kernel(const int* __restrict__ dur, int* __restrict__ cums)
{
    int b = blockIdx.x;
    if (threadIdx.x == 0) {
        int s = 0;
        for (int t = 0; t < TT; t++) { s += dur[b*TT + t]; cums[b*TT + t] = s; }
    }
}

__global__ __launch_bounds__(256) void regulate_kernel(const float* __restrict__ enc,
                                                       const int* __restrict__ cums,
                                                       const int* __restrict__ mellen,
                                                       float* __restrict__ dec_in,
                                                       __half* __restrict__ dec_inh)
{
    int bf = blockIdx.x;
    int b = bf / MELN, f = bf % MELN;
    const int* c = cums + b*TT;
    int lo = 0, hi = TT;
    while (lo < hi) { int mid = (lo + hi) >> 1; if (c[mid] <= f) lo = mid + 1; else hi = mid; }
    int idx = lo; if (idx > TT-1) idx = TT-1;
    float keep = (f <= mellen[b]) ? 1.f : 0.f;
    for (int d = threadIdx.x; d < DD; d += 256) {
        float v = enc[(size_t)(b*TT + idx)*DD + d] * keep;
        dec_in[(size_t)bf*DD + d]  = v;
        dec_inh[(size_t)bf*DD + d] = __float2half_rn(v);
    }
}

// =============================== host side ===============================
struct Ptrs {
    float *x, *ctx, *t1, *h2, *enc, *am, *am2;
    __half *xh, *qkvh, *ctxh, *hh, *wh, *whOut;
    int *cums;
};

static void get_ptrs(Ptrs& p)
{
    cudaGetSymbolAddress((void**)&p.x,     g_x);
    cudaGetSymbolAddress((void**)&p.xh,    g_xh);
    cudaGetSymbolAddress((void**)&p.qkvh,  g_qkvh);
    cudaGetSymbolAddress((void**)&p.ctx,   g_ctx);
    cudaGetSymbolAddress((void**)&p.ctxh,  g_ctxh);
    cudaGetSymbolAddress((void**)&p.t1,    g_t1);
    cudaGetSymbolAddress((void**)&p.hh,    g_hh);
    cudaGetSymbolAddress((void**)&p.h2,    g_h2);
    cudaGetSymbolAddress((void**)&p.enc,   g_enc);
    cudaGetSymbolAddress((void**)&p.am,    g_am);
    cudaGetSymbolAddress((void**)&p.am2,   g_am2);
    cudaGetSymbolAddress((void**)&p.wh,    g_wh);
    cudaGetSymbolAddress((void**)&p.whOut, g_whOut);
    cudaGetSymbolAddress((void**)&p.cums,  g_cums);
}

static void run_layer(Ptrs& p, int S, int sLog, const float* am, const __half* whl,
                      const float* bqkv, const float* bo,
                      const float* ln1g, const float* ln1b,
                      const float* c1b,  const float* c2b,
                      const float* ln2g, const float* ln2b)
{
    const int M = BB * S;
    const bool small = (S == TT);

    if (small)
        gemm_h<2><<<dim3(12, M/64), 256, H_SMEM_64>>>(p.xh, whl + WT_QKV, bqkv,
                                                      nullptr, p.qkvh,
                                                      M, 3*DD, DD, DD, sLog, 0, 0, 1, 0);
    else
        gemm_h<4><<<dim3(12, M/128), 256, H_SMEM_128>>>(p.xh, whl + WT_QKV, bqkv,
                                                        nullptr, p.qkvh,
                                                        M, 3*DD, DD, DD, sLog, 0, 0, 1, 0);

    flash_attn<<<dim3(S/128, BB*HH), 256, FA_SMEM_BYTES>>>(p.qkvh, am, p.ctxh, S);

    if (small)
        gemm_h<2><<<dim3(4, M/64), 256, H_SMEM_64>>>(p.ctxh, whl + WT_WO, bo,
                                                     p.t1, nullptr,
                                                     M, DD, DD, DD, sLog, 0, 0, 0, 0);
    else
        gemm_h<4><<<dim3(4, M/128), 256, H_SMEM_128>>>(p.ctxh, whl + WT_WO, bo,
                                                       p.t1, nullptr,
                                                       M, DD, DD, DD, sLog, 0, 0, 0, 0);

    add_ln_kernel<<<M/2, 256>>>(p.x, p.t1, ln1g, ln1b, p.ctx, p.xh);

    gemm_h<4><<<dim3(16, M/128), 256, H_SMEM_128>>>(p.xh, whl + WT_C1, c1b,
                                                    nullptr, p.hh,
                                                    M, INTERN, 3*DD, DD, sLog, 1, 1, 1, 0);
    if (small)
        gemm_h<2><<<dim3(4, M/64), 256, H_SMEM_64>>>(p.hh, whl + WT_C2, c2b,
                                                     p.h2, nullptr,
                                                     M, DD, 3*INTERN, INTERN, sLog, 1, 0, 0, 0);
    else
        gemm_h<4><<<dim3(4, M/128), 256, H_SMEM_128>>>(p.hh, whl + WT_C2, c2b,
                                                       p.h2, nullptr,
                                                       M, DD, 3*INTERN, INTERN, sLog, 1, 0, 0, 0);

    add_ln_kernel<<<M/2, 256>>>(p.ctx, p.h2, ln2g, ln2b, p.x, p.xh);
}

extern "C" void kernel_launch(void* const* d_in, const int* in_sizes, int n_in,
                              void* d_out, int out_size)
{
    const int*   tokens        = (const int*)  d_in[0];
    const int*   token_lengths = (const int*)  d_in[1];
    const int*   melspec_len   = (const int*)  d_in[2];
    const int*   durations     = (const int*)  d_in[3];
    const float* emb           = (const float*)d_in[5];
    const float* ew[12]; for (int i = 0; i < 12; i++) ew[i] = (const float*)d_in[6 + i];
    const float* dw[12]; for (int i = 0; i < 12; i++) dw[i] = (const float*)d_in[18 + i];
    const float* out_w         = (const float*)d_in[30];
    const float* out_b         = (const float*)d_in[31];

    cudaFuncSetAttribute(flash_attn, cudaFuncAttributeMaxDynamicSharedMemorySize,
                         FA_SMEM_BYTES);
    cudaFuncSetAttribute(gemm_h<4>, cudaFuncAttributeMaxDynamicSharedMemorySize,
                         H_SMEM_128);
    cudaFuncSetAttribute(gemm_h<2>, cudaFuncAttributeMaxDynamicSharedMemorySize,
                         H_SMEM_64);

    Ptrs p; get_ptrs(p);

    // ---- weight transpose + fp16 convert: enc+dec batched (z = 8 layers) ----
    transpose_wh2<<<dim3(16, 48, 2*LLAY), 256>>>(ew[0], dw[0], p.wh + WT_QKV,
                                                 DD, 3*DD, (size_t)DD*3*DD, WT_LAYER);
    transpose_wh2<<<dim3(16, 16, 2*LLAY), 256>>>(ew[2], dw[2], p.wh + WT_WO,
                                                 DD, DD, (size_t)DD*DD, WT_LAYER);
    transpose_wh2<<<dim3(48, 64, 2*LLAY), 256>>>(ew[6], dw[6], p.wh + WT_C1,
                                                 3*DD, INTERN, (size_t)3*DD*INTERN, WT_LAYER);
    transpose_wh2<<<dim3(192, 16, 2*LLAY), 256>>>(ew[8], dw[8], p.wh + WT_C2,
                                                  3*INTERN, DD, (size_t)3*INTERN*DD, WT_LAYER);
    transpose_whS<<<dim3(16, 3), 256>>>(out_w, p.whOut, DD, OUTC);

    // ---- embed + positional + encoder mask ----
    embed_kernel<<<(BB*TT*DD + 255)/256, 256>>>(tokens, emb, p.x, p.xh);
    mask_kernel<<<(BB*TT + 255)/256, 256>>>(token_lengths, p.am, TT);

    // ---- encoder stack (S = TT) ----
    for (int l = 0; l < LLAY; l++) {
        run_layer(p, TT, 8, p.am, p.wh + (size_t)l * WT_LAYER,
                  ew[1] + (size_t)l*3*DD,  ew[3] + (size_t)l*DD,
                  ew[4] + (size_t)l*DD,    ew[5] + (size_t)l*DD,
                  ew[7] + (size_t)l*INTERN, ew[9] + (size_t)l*DD,
                  ew[10] + (size_t)l*DD,   ew[11] + (size_t)l*DD);
    }

    // ---- length regulator ----
    cudaMemcpyAsync(p.enc, p.x, (size_t)BB*TT*DD*sizeof(float), cudaMemcpyDeviceToDevice);
    cumsum_kernel<<<BB, 32>>>(durations, p.cums);
    regulate_kernel<<<BB*MELN, 256>>>(p.enc, p.cums, melspec_len, p.x, p.xh);
    mask_kernel<<<(BB*MELN + 255)/256, 256>>>(melspec_len, p.am2, MELN);

    // ---- decoder stack (S = MELN) ----
    for (int l = 0; l < LLAY; l++) {
        run_layer(p, MELN, 10, p.am2, p.wh + (size_t)(LLAY + l) * WT_LAYER,
                  dw[1] + (size_t)l*3*DD,  dw[3] + (size_t)l*DD,
                  dw[4] + (size_t)l*DD,    dw[5] + (size_t)l*DD,
                  dw[7] + (size_t)l*INTERN, dw[9] + (size_t)l*DD,
                  dw[10] + (size_t)l*DD,   dw[11] + (size_t)l*DD);
    }

    // ---- output projection fused with transpose: writes (b, o, f) ----
    gemm_h<2><<<dim3(1, BB*MELN/64), 256, H_SMEM_64>>>(p.xh, p.whOut, out_b,
                                                       (float*)d_out, nullptr,
                                                       BB*MELN, OUTC, DD, DD, 10,
                                                       0, 0, 0, 1);
}